// round 6
// baseline (speedup 1.0000x reference)
#include <cuda_runtime.h>
#include <cuda_bf16.h>
#include <cstdint>

#define BATCH 4
#define CH    128
#define CINR  1024
#define NN    256
#define HH    120
#define WW    160
#define HWSZ  (HH*WW)

#define KC    32
#define CTA_M 128
#define CTA_N 128
#define SROW  40

// ---------------- scratch (device globals; no allocations allowed) ----------
__device__ float g_depA[BATCH*2*CH*HWSZ];
__device__ float g_depB[BATCH*2*CH*HWSZ];
__device__ float g_imgA[BATCH*CH*HWSZ];
__device__ float g_relA[BATCH*CH*HWSZ];
__device__ float g_relB[BATCH*CH*HWSZ];
__device__ float g_hmid[BATCH*CH*NN];
__device__ float g_relmap[BATCH*CH*NN];
__device__ float g_wpack[2506752];

// pack-section offsets (floats)
#define WP1 0
#define WP2 589824
#define WP3 1032192
#define WP4 1474560
#define WP5 2064384
#define WP6 2359296

// ---------------- helpers ----------------------------------------------------
__device__ __forceinline__ float tf32r(float x){
    float y;
    asm("cvt.rna.tf32.f32 %0, %1;" : "=f"(y) : "f"(x));
    return y;
}
__device__ __forceinline__ void mma8(float* d, const float* a, const float* b){
    const uint32_t* A = (const uint32_t*)a;
    const uint32_t* B = (const uint32_t*)b;
    asm volatile(
        "mma.sync.aligned.m16n8k8.row.col.f32.tf32.tf32.f32 "
        "{%0,%1,%2,%3},{%4,%5,%6,%7},{%8,%9},{%0,%1,%2,%3};\n"
        : "+f"(d[0]), "+f"(d[1]), "+f"(d[2]), "+f"(d[3])
        : "r"(A[0]), "r"(A[1]), "r"(A[2]), "r"(A[3]), "r"(B[0]), "r"(B[1]));
}

// ---------------- weight pack: tf32 cvt + MMA column permutation ------------
__global__ void pack_kernel(float* __restrict__ dst,
                            const float* __restrict__ W1, int K1,
                            const float* __restrict__ W2, int K2,
                            int Cout)
{
    const int Kt = K1 + K2;
    const int total = Cout * Kt;
    for (int idx = blockIdx.x * blockDim.x + threadIdx.x; idx < total;
         idx += gridDim.x * blockDim.x) {
        const int co = idx / Kt;
        const int kg = idx - co * Kt;
        float v = (kg < K1) ? W1[(size_t)co * K1 + kg]
                            : W2[(size_t)co * K2 + (kg - K1)];
        const int cb  = kg & ~31;
        const int w   = kg & 31;
        const int s   = w >> 3;
        const int ks  = w & 7;
        const int col = s * 8 + 2 * (ks & 3) + (ks >> 2);
        dst[(size_t)co * Kt + cb + col] = tf32r(v);
    }
}

// ---------------- 1x1 conv == channel matmul --------------------------------
__global__ void mm_kernel(const float* __restrict__ X, const float* __restrict__ Wm,
                          const float* __restrict__ bias, float* __restrict__ out,
                          int Cin, int do_relu)
{
    const int o = blockIdx.x;
    const int b = blockIdx.y;
    const int n = threadIdx.x;
    const float* xp = X + ((size_t)b * Cin) * NN + n;
    const float* wp = Wm + (size_t)o * Cin;
    float acc = bias[o];
    #pragma unroll 4
    for (int c = 0; c < Cin; ++c)
        acc = fmaf(wp[c], xp[(size_t)c * NN], acc);
    if (do_relu) acc = fmaxf(acc, 0.f);
    out[((size_t)b * CH + o) * NN + n] = acc;
}

// ---------------- box scatter of interpolated relation rows -----------------
__global__ void scatter_kernel(const float* __restrict__ relmap,
                               const int* __restrict__ bbox,
                               float* __restrict__ rel)
{
    __shared__ float row[64 * 161];
    const int y  = blockIdx.x;
    const int b  = blockIdx.y;
    const int c0 = blockIdx.z * 64;
    const int c  = threadIdx.x;

    float* myrow = row + c * 161;
    #pragma unroll
    for (int x = 0; x < 161; ++x) myrow[x] = 0.f;

    const float* rm = relmap + ((size_t)(b * CH + c0 + c)) * NN;

    for (int n = 0; n < NN; ++n) {
        const int* bb = bbox + ((size_t)b * NN + n) * 8;
        int sx1 = bb[0] >> 1, sy1 = bb[1] >> 1, sx2 = bb[2] >> 1, sy2 = bb[3] >> 1;
        int ox1 = bb[4] >> 1, oy1 = bb[5] >> 1, ox2 = bb[6] >> 1, oy2 = bb[7] >> 1;
        int sh = sy2 - sy1, sw = sx2 - sx1;
        int oh = oy2 - oy1, ow = ox2 - ox1;
        if (!(sh >= 5 && sw >= 5 && oh >= 5 && ow >= 5)) continue;

        if (y >= sy1 && y < sy2) {
            int s = (y - sy1) * 256 / sh;  s = min(s, 255);
            float v = rm[s];
            myrow[sx1] += v;
            myrow[sx2] -= v;
        }
        if (y >= oy1 && y < oy2) {
            int s = (y - oy1) * 256 / oh;  s = min(s, 255);
            float v = rm[s];
            myrow[ox1] += v;
            myrow[ox2] -= v;
        }
    }

    float run = 0.f;
    float* op = rel + (((size_t)(b * CH + c0 + c)) * HH + y) * WW;
    #pragma unroll 4
    for (int x = 0; x < WW; ++x) { run += myrow[x]; op[x] = run; }
}

// ============ tf32 mma.sync implicit-GEMM 3-segment 3x3 SAME conv ===========
// 256 threads, warp grid 2(m) x 4(n), warp tile 64x32.
// base is split into two 128-channel halves (baseLo / baseHi, batch strides).
__global__ void __launch_bounds__(256, 2)
conv_mma(float* __restrict__ outp,
         const float* __restrict__ baseLo, const float* __restrict__ baseHi,
         size_t bsLo, size_t bsHi,
         const float* __restrict__ X0, int C0,
         const float* __restrict__ X1, int C1,
         const float* __restrict__ X2, int C2,
         const float* __restrict__ wp,
         const float* __restrict__ B1,
         int Cout, float scale, int do_relu)
{
    __shared__ float sA[CTA_M * SROW];
    __shared__ float sB[CTA_N * SROW];

    const int tid  = threadIdx.x;
    const int lane = tid & 31;
    const int wid  = tid >> 5;
    const int g    = lane >> 2;
    const int c    = lane & 3;
    const int wm   = wid >> 2;      // 0..1
    const int wn   = wid & 3;       // 0..3

    const int n0  = blockIdx.x * CTA_N;
    const int co0 = blockIdx.y * CTA_M;
    const int b   = blockIdx.z;
    const int Kt  = (C0 + C1 + C2) * 9;

    // B staging: thread handles quad q (4 k's) x 4 pixels
    const int k4 = tid >> 5;            // 0..7
    const int nb = tid & 31;            // 0..31
    const int q  = (k4 + nb) & 7;
    int kq[4];
    {
        const int s = q >> 1;
        #pragma unroll
        for (int m = 0; m < 4; ++m) {
            const int cs = (q & 1) * 4 + m;
            kq[m] = s * 8 + (cs >> 1) + 4 * (cs & 1);
        }
    }

    int nfix[4];
    int vmask[4];
    #pragma unroll
    for (int j = 0; j < 4; ++j) {
        const int n = n0 + nb + 32 * j;
        const int y = n / WW;
        const int x = n - y * WW;
        nfix[j]  = n - (WW + 1);
        vmask[j] = (y > 0) | ((y < HH - 1) << 1) | ((x > 0) << 2) | ((x < WW - 1) << 3);
    }

    float acc[4][4][4];
    #pragma unroll
    for (int mi = 0; mi < 4; ++mi)
        #pragma unroll
        for (int nj = 0; nj < 4; ++nj)
            #pragma unroll
            for (int t = 0; t < 4; ++t) acc[mi][nj][t] = 0.f;

    int gk = 0;
    #pragma unroll 1
    for (int seg = 0; seg < 3; ++seg) {
        const float* X = (seg == 0) ? X0 : (seg == 1) ? X1 : X2;
        const int    C = (seg == 0) ? C0 : (seg == 1) ? C1 : C2;
        if (C == 0) continue;
        const float* Xb = X + (size_t)b * C * HWSZ;
        const int nch = (C * 9) >> 5;

        #pragma unroll 1
        for (int cc = 0; cc < nch; ++cc, ++gk) {
            const int k0 = cc * KC;
            const int wcol0 = gk * KC;
            __syncthreads();

            // ---- stage A: vector copy of packed weights ----
            #pragma unroll
            for (int j = 0; j < 4; ++j) {
                const int e  = tid + j * 256;
                const int co = e >> 3;
                const int qq = e & 7;
                const float4 v = *(const float4*)(wp + (size_t)(co0 + co) * Kt
                                                  + wcol0 + qq * 4);
                *(float4*)&sA[co * SROW + qq * 4] = v;
            }

            // ---- stage B: im2col gather, one STS.128 per pixel ----
            int kb[4], req[4];
            #pragma unroll
            for (int i = 0; i < 4; ++i) {
                const int k   = k0 + kq[i];
                const int ci  = k / 9;
                const int tap = k - ci * 9;
                const int dy  = tap / 3;
                const int dx  = tap - dy * 3;
                kb[i]  = ci * HWSZ + dy * WW + dx;
                req[i] = (dy == 0 ? 1 : (dy == 2 ? 2 : 0)) |
                         (dx == 0 ? 4 : (dx == 2 ? 8 : 0));
            }
            #pragma unroll
            for (int j = 0; j < 4; ++j) {
                float4 v;
                float* pv = (float*)&v;
                #pragma unroll
                for (int i = 0; i < 4; ++i) {
                    float t = 0.f;
                    if ((vmask[j] & req[i]) == req[i]) t = Xb[kb[i] + nfix[j]];
                    pv[i] = tf32r(t);
                }
                *(float4*)&sB[(nb + 32 * j) * SROW + q * 4] = v;
            }
            __syncthreads();

            // ---- MMA over 4 k-slices ----
            #pragma unroll
            for (int s = 0; s < 4; ++s) {
                float af[4][4];
                float bf[4][2];
                #pragma unroll
                for (int mi = 0; mi < 4; ++mi) {
                    const int r = wm * 64 + mi * 16 + g;
                    const float2 p  = *(const float2*)&sA[r * SROW + s * 8 + 2 * c];
                    const float2 qd = *(const float2*)&sA[(r + 8) * SROW + s * 8 + 2 * c];
                    af[mi][0] = p.x;  af[mi][1] = qd.x;
                    af[mi][2] = p.y;  af[mi][3] = qd.y;
                }
                #pragma unroll
                for (int nj = 0; nj < 4; ++nj) {
                    const int r = wn * 32 + nj * 8 + g;
                    const float2 p = *(const float2*)&sB[r * SROW + s * 8 + 2 * c];
                    bf[nj][0] = p.x;  bf[nj][1] = p.y;
                }
                #pragma unroll
                for (int mi = 0; mi < 4; ++mi)
                    #pragma unroll
                    for (int nj = 0; nj < 4; ++nj)
                        mma8(acc[mi][nj], af[mi], bf[nj]);
            }
        }
    }

    // ---- epilogue ----
    const float* bp = (co0 == 0) ? baseLo : baseHi;
    const size_t bs = (co0 == 0) ? bsLo : bsHi;
    #pragma unroll
    for (int mi = 0; mi < 4; ++mi) {
        const int coa = co0 + wm * 64 + mi * 16 + g;
        const int cob = coa + 8;
        const float ba = B1[coa];
        const float bb = B1[cob];
        #pragma unroll
        for (int nj = 0; nj < 4; ++nj) {
            const int pix = n0 + wn * 32 + nj * 8 + 2 * c;
            const size_t oa = ((size_t)(b * Cout + coa)) * HWSZ + pix;
            const size_t ob = ((size_t)(b * Cout + cob)) * HWSZ + pix;
            float2 r0, r1;
            r0.x = acc[mi][nj][0] + ba;  r0.y = acc[mi][nj][1] + ba;
            r1.x = acc[mi][nj][2] + bb;  r1.y = acc[mi][nj][3] + bb;
            if (bp) {
                const size_t pa = b * bs + (size_t)(coa - co0) * HWSZ + pix;
                const size_t pb = b * bs + (size_t)(cob - co0) * HWSZ + pix;
                const float2 s0 = *(const float2*)(bp + pa);
                const float2 s1 = *(const float2*)(bp + pb);
                r0.x = fmaf(scale, r0.x, s0.x);  r0.y = fmaf(scale, r0.y, s0.y);
                r1.x = fmaf(scale, r1.x, s1.x);  r1.y = fmaf(scale, r1.y, s1.y);
            } else {
                r0.x *= scale; r0.y *= scale;
                r1.x *= scale; r1.y *= scale;
            }
            if (do_relu) {
                r0.x = fmaxf(r0.x, 0.f); r0.y = fmaxf(r0.y, 0.f);
                r1.x = fmaxf(r1.x, 0.f); r1.y = fmaxf(r1.y, 0.f);
            }
            *(float2*)(outp + oa) = r0;
            *(float2*)(outp + ob) = r1;
        }
    }
}

// ---------------- bias combine (B1 + B2 once, on device) --------------------
__global__ void bias_add(float* __restrict__ dst, const float* __restrict__ a,
                         const float* __restrict__ b, int n)
{
    int i = blockIdx.x * blockDim.x + threadIdx.x;
    if (i < n) dst[i] = a[i] + (b ? b[i] : 0.f);
}
__device__ float g_bias[6 * 256];

static void conv3(float* out,
                  const float* baseLo, const float* baseHi,
                  size_t bsLo, size_t bsHi,
                  const float* X0, int C0, const float* X1, int C1,
                  const float* X2, int C2,
                  const float* wp, const float* bias,
                  int Cout, float scale, int relu)
{
    dim3 g(HWSZ / CTA_N, Cout / CTA_M, BATCH);
    conv_mma<<<g, 256>>>(out, baseLo, baseHi, bsLo, bsHi,
                         X0, C0, X1, C1, X2, C2, wp, bias, Cout, scale, relu);
}

// ---------------------------------------------------------------------------
extern "C" void kernel_launch(void* const* d_in, const int* in_sizes, int n_in,
                              void* d_out, int out_size)
{
    const float* img_in  = (const float*)d_in[0];
    const float* tf      = (const float*)d_in[1];
    const float* rw1     = (const float*)d_in[2];
    const float* rb1     = (const float*)d_in[3];
    const float* rw2     = (const float*)d_in[4];
    const float* rb2     = (const float*)d_in[5];
    const float* dmc_w   = (const float*)d_in[6];
    const float* dmc_b   = (const float*)d_in[7];
    const float* imc_w01 = (const float*)d_in[8];
    const float* imc_b01 = (const float*)d_in[9];
    const float* imc_w23 = (const float*)d_in[10];
    const float* imc_b23 = (const float*)d_in[11];
    const float* rmc_w01 = (const float*)d_in[12];
    const float* rmc_b01 = (const float*)d_in[13];
    const float* rmc_w23 = (const float*)d_in[14];
    const float* rmc_b23 = (const float*)d_in[15];
    const float* emb_w1  = (const float*)d_in[16];
    const float* emb_b1  = (const float*)d_in[17];
    const float* emb_w2  = (const float*)d_in[18];
    const float* emb_b2  = (const float*)d_in[19];
    const int*   bbox    = (const int*)d_in[20];
    float* out = (float*)d_out;

    float *depA, *depB, *imgA, *relA, *relB, *hmid, *relmap, *wpk, *bia;
    cudaGetSymbolAddress((void**)&depA, g_depA);
    cudaGetSymbolAddress((void**)&depB, g_depB);
    cudaGetSymbolAddress((void**)&imgA, g_imgA);
    cudaGetSymbolAddress((void**)&relA, g_relA);
    cudaGetSymbolAddress((void**)&relB, g_relB);
    cudaGetSymbolAddress((void**)&hmid, g_hmid);
    cudaGetSymbolAddress((void**)&relmap, g_relmap);
    cudaGetSymbolAddress((void**)&wpk, g_wpack);
    cudaGetSymbolAddress((void**)&bia, g_bias);

    const size_t WB = (size_t)2 * CH * CH * 9;
    const size_t SB = (size_t)CH * HWSZ;   // one 128-ch map, batch stride

    // 0) pack + convert weights; combine biases
    pack_kernel<<<512, 256>>>(wpk + WP1, dmc_w + 0 * WB, 1152,
                              dmc_w + 2 * WB, 1152, 256);
    pack_kernel<<<512, 256>>>(wpk + WP2, imc_w01, 2304, imc_w23, 1152, 128);
    pack_kernel<<<512, 256>>>(wpk + WP3, rmc_w01, 2304, rmc_w23, 1152, 128);
    pack_kernel<<<512, 256>>>(wpk + WP4, dmc_w + 1 * WB, 1152,
                              dmc_w + 3 * WB, 1152, 256);
    pack_kernel<<<512, 256>>>(wpk + WP5, emb_w1, 2304, (const float*)0, 0, 128);
    pack_kernel<<<512, 256>>>(wpk + WP6, emb_w2, 1152, (const float*)0, 0, 128);

    bias_add<<<1, 256>>>(bia + 0 * 256, dmc_b + 0 * 256, dmc_b + 2 * 256, 256);
    bias_add<<<1, 128>>>(bia + 1 * 256, imc_b01, imc_b23, 128);
    bias_add<<<1, 128>>>(bia + 2 * 256, rmc_b01, rmc_b23, 128);
    bias_add<<<1, 256>>>(bia + 3 * 256, dmc_b + 1 * 256, dmc_b + 3 * 256, 256);
    bias_add<<<1, 128>>>(bia + 4 * 256, emb_b1, (const float*)0, 128);
    bias_add<<<1, 128>>>(bia + 5 * 256, emb_b2, (const float*)0, 128);

    // 1) rel embedding: two channel matmuls
    mm_kernel<<<dim3(CH, BATCH), NN>>>(tf,   rw1, rb1, hmid,   CINR, 1);
    mm_kernel<<<dim3(CH, BATCH), NN>>>(hmid, rw2, rb2, relmap, CH,   0);

    // 2) scatter interpolated rows into rel map (writes every element)
    scatter_kernel<<<dim3(HH, BATCH, 2), 64>>>(relmap, bbox, relA);

    // 3) TriGraph iteration 0 (dep never materialized; segments read directly)
    conv3(depB, img_in, relA, SB, SB,
          img_in, CH, relA, CH, nullptr, 0,
          wpk + WP1, bia + 0 * 256, 2 * CH, 0.5f, 1);
    conv3(imgA, img_in, nullptr, SB, 0,
          img_in, CH, relA, CH, relA, CH,
          wpk + WP2, bia + 1 * 256, CH, 0.5f, 1);
    conv3(relB, relA, nullptr, SB, 0,
          img_in, CH, relA, CH, img_in, CH,
          wpk + WP3, bia + 2 * 256, CH, 0.5f, 1);

    // 4) TriGraph iteration 1: only dep feeds the output
    conv3(depA, depB, depB + CH * HWSZ, 2 * SB, 2 * SB,
          imgA, CH, relB, CH, nullptr, 0,
          wpk + WP4, bia + 3 * 256, 2 * CH, 0.5f, 1);

    // 5) final embedding (imgA is dead after step 4 -> reuse)
    conv3(imgA, nullptr, nullptr, 0, 0,
          depA, 2 * CH, nullptr, 0, nullptr, 0,
          wpk + WP5, bia + 4 * 256, CH, 1.f, 1);
    conv3(out, nullptr, nullptr, 0, 0,
          imgA, CH, nullptr, 0, nullptr, 0,
          wpk + WP6, bia + 5 * 256, CH, 1.f, 0);
}

// round 7
// speedup vs baseline: 1.1800x; 1.1800x over previous
#include <cuda_runtime.h>
#include <cuda_fp16.h>
#include <cstdint>

#define BATCH 4
#define CH    128
#define CINR  1024
#define NN    256
#define HH    120
#define WW    160
#define HWSZ  (HH*WW)

#define KC    32
#define CTA_M 128
#define CTA_N 128

// ---------------- scratch (device globals; no allocations allowed) ----------
__device__ float  g_depA[BATCH*2*CH*HWSZ];
__device__ float  g_depB[BATCH*2*CH*HWSZ];
__device__ float  g_imgA[BATCH*CH*HWSZ];
__device__ float  g_relA[BATCH*CH*HWSZ];
__device__ float  g_relB[BATCH*CH*HWSZ];
__device__ float  g_hmid[BATCH*CH*NN];
__device__ float  g_relmap[BATCH*CH*NN];
__device__ __half g_wpack[2506752];
__device__ float  g_bias[6 * 256];

// pack-section offsets (halves)
#define WP1 0
#define WP2 589824
#define WP3 1032192
#define WP4 1474560
#define WP5 2064384
#define WP6 2359296

// ---------------- helpers ----------------------------------------------------
__device__ __forceinline__ uint32_t pkh2(float a, float b){
    __half2 h = __floats2half2_rn(a, b);
    return *(uint32_t*)&h;
}
__device__ __forceinline__ void mma16(float* d, uint32_t a0, uint32_t a1,
                                      uint32_t a2, uint32_t a3,
                                      uint32_t b0, uint32_t b1){
    asm volatile(
        "mma.sync.aligned.m16n8k16.row.col.f32.f16.f16.f32 "
        "{%0,%1,%2,%3},{%4,%5,%6,%7},{%8,%9},{%0,%1,%2,%3};\n"
        : "+f"(d[0]), "+f"(d[1]), "+f"(d[2]), "+f"(d[3])
        : "r"(a0), "r"(a1), "r"(a2), "r"(a3), "r"(b0), "r"(b1));
}

// ---------------- weight pack: fp16 cvt + MMA layout + row XOR swizzle ------
// Within each 32-k chunk: s=k>>4 (k16 slice), kk=k&15, hi=kk>>3, c=(kk&7)>>1,
// par=kk&1. Stored half position = (c ^ (co&3))*8 + s*4 + hi*2 + par.
__global__ void pack_kernel(__half* __restrict__ dst,
                            const float* __restrict__ W1, int K1,
                            const float* __restrict__ W2, int K2,
                            int Cout)
{
    const int Kt = K1 + K2;
    const int total = Cout * Kt;
    for (int idx = blockIdx.x * blockDim.x + threadIdx.x; idx < total;
         idx += gridDim.x * blockDim.x) {
        const int co = idx / Kt;
        const int kg = idx - co * Kt;
        float v = (kg < K1) ? W1[(size_t)co * K1 + kg]
                            : W2[(size_t)co * K2 + (kg - K1)];
        const int cb  = kg & ~31;
        const int w   = kg & 31;
        const int s   = w >> 4;
        const int kk  = w & 15;
        const int hi  = kk >> 3;
        const int c   = (kk & 7) >> 1;
        const int par = kk & 1;
        const int csw = c ^ (co & 3);
        dst[(size_t)co * Kt + cb + csw * 8 + s * 4 + hi * 2 + par] =
            __float2half_rn(v);
    }
}

// ---------------- 1x1 conv == channel matmul --------------------------------
__global__ void mm_kernel(const float* __restrict__ X, const float* __restrict__ Wm,
                          const float* __restrict__ bias, float* __restrict__ out,
                          int Cin, int do_relu)
{
    const int o = blockIdx.x;
    const int b = blockIdx.y;
    const int n = threadIdx.x;
    const float* xp = X + ((size_t)b * Cin) * NN + n;
    const float* wp = Wm + (size_t)o * Cin;
    float acc = bias[o];
    #pragma unroll 4
    for (int c = 0; c < Cin; ++c)
        acc = fmaf(wp[c], xp[(size_t)c * NN], acc);
    if (do_relu) acc = fmaxf(acc, 0.f);
    out[((size_t)b * CH + o) * NN + n] = acc;
}

// ---------------- box scatter of interpolated relation rows -----------------
__global__ void scatter_kernel(const float* __restrict__ relmap,
                               const int* __restrict__ bbox,
                               float* __restrict__ rel)
{
    __shared__ float row[64 * 161];
    const int y  = blockIdx.x;
    const int b  = blockIdx.y;
    const int c0 = blockIdx.z * 64;
    const int c  = threadIdx.x;

    float* myrow = row + c * 161;
    #pragma unroll
    for (int x = 0; x < 161; ++x) myrow[x] = 0.f;

    const float* rm = relmap + ((size_t)(b * CH + c0 + c)) * NN;

    for (int n = 0; n < NN; ++n) {
        const int* bb = bbox + ((size_t)b * NN + n) * 8;
        int sx1 = bb[0] >> 1, sy1 = bb[1] >> 1, sx2 = bb[2] >> 1, sy2 = bb[3] >> 1;
        int ox1 = bb[4] >> 1, oy1 = bb[5] >> 1, ox2 = bb[6] >> 1, oy2 = bb[7] >> 1;
        int sh = sy2 - sy1, sw = sx2 - sx1;
        int oh = oy2 - oy1, ow = ox2 - ox1;
        if (!(sh >= 5 && sw >= 5 && oh >= 5 && ow >= 5)) continue;

        if (y >= sy1 && y < sy2) {
            int s = (y - sy1) * 256 / sh;  s = min(s, 255);
            float v = rm[s];
            myrow[sx1] += v;
            myrow[sx2] -= v;
        }
        if (y >= oy1 && y < oy2) {
            int s = (y - oy1) * 256 / oh;  s = min(s, 255);
            float v = rm[s];
            myrow[ox1] += v;
            myrow[ox2] -= v;
        }
    }

    float run = 0.f;
    float* op = rel + (((size_t)(b * CH + c0 + c)) * HH + y) * WW;
    #pragma unroll 4
    for (int x = 0; x < WW; ++x) { run += myrow[x]; op[x] = run; }
}

// ============ fp16 mma.sync implicit-GEMM 3-segment 3x3 SAME conv ===========
// 128 threads, warp grid 2(m) x 2(n), warp tile 64x64, m16n8k16.
// smem rows: 32 halves (64B) dense, XOR swizzle c^=(row&3) on 16B quads.
__global__ void __launch_bounds__(128, 2)
conv_mma(float* __restrict__ outp,
         const float* __restrict__ baseLo, const float* __restrict__ baseHi,
         size_t bsLo, size_t bsHi,
         const float* __restrict__ X0, int C0,
         const float* __restrict__ X1, int C1,
         const float* __restrict__ X2, int C2,
         const __half* __restrict__ wp,
         const float* __restrict__ B1,
         int Cout, float scale, int do_relu)
{
    __shared__ __half sA[CTA_M * 32];
    __shared__ __half sB[CTA_N * 32];

    const int tid  = threadIdx.x;
    const int lane = tid & 31;
    const int wid  = tid >> 5;
    const int g    = lane >> 2;
    const int c    = lane & 3;
    const int wm   = wid >> 1;      // 0..1
    const int wn   = wid & 1;       // 0..1

    const int n0  = blockIdx.x * CTA_N;
    const int co0 = blockIdx.y * CTA_M;
    const int b   = blockIdx.z;
    const int Kt  = (C0 + C1 + C2) * 9;

    // B staging: thread handles fixed c-quad, pixels nbase + 32*j
    const int cs    = tid & 3;
    const int nbase = tid >> 2;     // 0..31

    int nfix[4];
    int vmask[4];
    #pragma unroll
    for (int j = 0; j < 4; ++j) {
        const int n = n0 + nbase + 32 * j;
        const int y = n / WW;
        const int x = n - y * WW;
        nfix[j]  = n - (WW + 1);
        vmask[j] = (y > 0) | ((y < HH - 1) << 1) | ((x > 0) << 2) | ((x < WW - 1) << 3);
    }

    const int fsw = (c ^ (g & 3)) * 8;     // frag-load swizzled quad (halves)

    float acc[4][8][4];
    #pragma unroll
    for (int mi = 0; mi < 4; ++mi)
        #pragma unroll
        for (int nj = 0; nj < 8; ++nj)
            #pragma unroll
            for (int t = 0; t < 4; ++t) acc[mi][nj][t] = 0.f;

    int gk = 0;
    #pragma unroll 1
    for (int seg = 0; seg < 3; ++seg) {
        const float* X = (seg == 0) ? X0 : (seg == 1) ? X1 : X2;
        const int    C = (seg == 0) ? C0 : (seg == 1) ? C1 : C2;
        if (C == 0) continue;
        const float* Xb = X + (size_t)b * C * HWSZ;
        const int nch = (C * 9) >> 5;

        #pragma unroll 1
        for (int cc = 0; cc < nch; ++cc, ++gk) {
            const int k0 = cc * KC;
            const int wcol0 = gk * KC;
            __syncthreads();

            // ---- stage A: linear copy of packed fp16 weights (8KB) ----
            #pragma unroll
            for (int j = 0; j < 2; ++j) {
                const int e = tid + j * 128;        // 256 x 16B items? no: 512/...
                // 128 rows x 64B = 8KB = 512 x 16B items; 128 threads x 4
                const int e0 = e;
                const int r0 = e0 >> 1;             // 2 x 32B? use 32B per item
                // simpler: each thread copies 2 x 32B below
                (void)r0;
            }
            {
                // 8KB / 128 threads = 64B per thread: one row each
                const int r = tid;
                const uint4* src = (const uint4*)(wp + (size_t)(co0 + r) * Kt + wcol0);
                uint4* dst = (uint4*)(sA + r * 32);
                dst[0] = src[0];
                dst[1] = src[1];
                dst[2] = src[2];
                dst[3] = src[3];
            }

            // ---- decode this thread's 8 k values (fixed c-quad) ----
            int kb[8], req[8];
            #pragma unroll
            for (int m = 0; m < 8; ++m) {
                const int s   = m >> 2;
                const int hi  = (m >> 1) & 1;
                const int par = m & 1;
                const int k   = k0 + s * 16 + hi * 8 + 2 * cs + par;
                const int ci  = k / 9;
                const int tap = k - ci * 9;
                const int dy  = tap / 3;
                const int dx  = tap - dy * 3;
                kb[m]  = ci * HWSZ + dy * WW + dx;
                req[m] = (dy == 0 ? 1 : (dy == 2 ? 2 : 0)) |
                         (dx == 0 ? 4 : (dx == 2 ? 8 : 0));
            }

            // ---- stage B: gather 8 floats -> 4 half2 -> STS.128 ----
            #pragma unroll
            for (int j = 0; j < 4; ++j) {
                const int n = nbase + 32 * j;
                float f[8];
                #pragma unroll
                for (int m = 0; m < 8; ++m) {
                    f[m] = 0.f;
                    if ((vmask[j] & req[m]) == req[m]) f[m] = Xb[kb[m] + nfix[j]];
                }
                uint4 v;
                v.x = pkh2(f[0], f[1]);
                v.y = pkh2(f[2], f[3]);
                v.z = pkh2(f[4], f[5]);
                v.w = pkh2(f[6], f[7]);
                const int csw = (cs ^ (n & 3)) * 8;
                *(uint4*)(sB + n * 32 + csw) = v;
            }
            __syncthreads();

            // ---- fragment loads (LDS.128 covers both k16 slices) ----
            uint4 alo[4], ahi[4], bfr[8];
            #pragma unroll
            for (int mi = 0; mi < 4; ++mi) {
                const int r = wm * 64 + mi * 16 + g;
                alo[mi] = *(const uint4*)(sA + r * 32 + fsw);
                ahi[mi] = *(const uint4*)(sA + (r + 8) * 32 + fsw);
            }
            #pragma unroll
            for (int nj = 0; nj < 8; ++nj) {
                const int r = wn * 64 + nj * 8 + g;
                bfr[nj] = *(const uint4*)(sB + r * 32 + fsw);
            }
            // ---- 2 slices x 4mi x 8nj mma ----
            #pragma unroll
            for (int mi = 0; mi < 4; ++mi)
                #pragma unroll
                for (int nj = 0; nj < 8; ++nj)
                    mma16(acc[mi][nj], alo[mi].x, ahi[mi].x, alo[mi].y, ahi[mi].y,
                          bfr[nj].x, bfr[nj].y);
            #pragma unroll
            for (int mi = 0; mi < 4; ++mi)
                #pragma unroll
                for (int nj = 0; nj < 8; ++nj)
                    mma16(acc[mi][nj], alo[mi].z, ahi[mi].z, alo[mi].w, ahi[mi].w,
                          bfr[nj].z, bfr[nj].w);
        }
    }

    // ---- epilogue ----
    const float* bp = (co0 == 0) ? baseLo : baseHi;
    const size_t bs = (co0 == 0) ? bsLo : bsHi;
    #pragma unroll
    for (int mi = 0; mi < 4; ++mi) {
        const int coa = co0 + wm * 64 + mi * 16 + g;
        const int cob = coa + 8;
        const float ba = B1[coa];
        const float bb = B1[cob];
        #pragma unroll
        for (int nj = 0; nj < 8; ++nj) {
            const int pix = n0 + wn * 64 + nj * 8 + 2 * c;
            const size_t oa = ((size_t)(b * Cout + coa)) * HWSZ + pix;
            const size_t ob = ((size_t)(b * Cout + cob)) * HWSZ + pix;
            float2 r0, r1;
            r0.x = acc[mi][nj][0] + ba;  r0.y = acc[mi][nj][1] + ba;
            r1.x = acc[mi][nj][2] + bb;  r1.y = acc[mi][nj][3] + bb;
            if (bp) {
                const size_t pa = b * bs + (size_t)(coa - co0) * HWSZ + pix;
                const size_t pb = b * bs + (size_t)(cob - co0) * HWSZ + pix;
                const float2 s0 = *(const float2*)(bp + pa);
                const float2 s1 = *(const float2*)(bp + pb);
                r0.x = fmaf(scale, r0.x, s0.x);  r0.y = fmaf(scale, r0.y, s0.y);
                r1.x = fmaf(scale, r1.x, s1.x);  r1.y = fmaf(scale, r1.y, s1.y);
            } else {
                r0.x *= scale; r0.y *= scale;
                r1.x *= scale; r1.y *= scale;
            }
            if (do_relu) {
                r0.x = fmaxf(r0.x, 0.f); r0.y = fmaxf(r0.y, 0.f);
                r1.x = fmaxf(r1.x, 0.f); r1.y = fmaxf(r1.y, 0.f);
            }
            *(float2*)(outp + oa) = r0;
            *(float2*)(outp + ob) = r1;
        }
    }
}

// ---------------- bias combine ----------------------------------------------
__global__ void bias_add(float* __restrict__ dst, const float* __restrict__ a,
                         const float* __restrict__ b, int n)
{
    int i = blockIdx.x * blockDim.x + threadIdx.x;
    if (i < n) dst[i] = a[i] + (b ? b[i] : 0.f);
}

static void conv3(float* out,
                  const float* baseLo, const float* baseHi,
                  size_t bsLo, size_t bsHi,
                  const float* X0, int C0, const float* X1, int C1,
                  const float* X2, int C2,
                  const __half* wp, const float* bias,
                  int Cout, float scale, int relu)
{
    dim3 g(HWSZ / CTA_N, Cout / CTA_M, BATCH);
    conv_mma<<<g, 128>>>(out, baseLo, baseHi, bsLo, bsHi,
                         X0, C0, X1, C1, X2, C2, wp, bias, Cout, scale, relu);
}

// ---------------------------------------------------------------------------
extern "C" void kernel_launch(void* const* d_in, const int* in_sizes, int n_in,
                              void* d_out, int out_size)
{
    const float* img_in  = (const float*)d_in[0];
    const float* tf      = (const float*)d_in[1];
    const float* rw1     = (const float*)d_in[2];
    const float* rb1     = (const float*)d_in[3];
    const float* rw2     = (const float*)d_in[4];
    const float* rb2     = (const float*)d_in[5];
    const float* dmc_w   = (const float*)d_in[6];
    const float* dmc_b   = (const float*)d_in[7];
    const float* imc_w01 = (const float*)d_in[8];
    const float* imc_b01 = (const float*)d_in[9];
    const float* imc_w23 = (const float*)d_in[10];
    const float* imc_b23 = (const float*)d_in[11];
    const float* rmc_w01 = (const float*)d_in[12];
    const float* rmc_b01 = (const float*)d_in[13];
    const float* rmc_w23 = (const float*)d_in[14];
    const float* rmc_b23 = (const float*)d_in[15];
    const float* emb_w1  = (const float*)d_in[16];
    const float* emb_b1  = (const float*)d_in[17];
    const float* emb_w2  = (const float*)d_in[18];
    const float* emb_b2  = (const float*)d_in[19];
    const int*   bbox    = (const int*)d_in[20];
    float* out = (float*)d_out;

    float *depA, *depB, *imgA, *relA, *relB, *hmid, *relmap, *bia;
    __half* wpk;
    cudaGetSymbolAddress((void**)&depA, g_depA);
    cudaGetSymbolAddress((void**)&depB, g_depB);
    cudaGetSymbolAddress((void**)&imgA, g_imgA);
    cudaGetSymbolAddress((void**)&relA, g_relA);
    cudaGetSymbolAddress((void**)&relB, g_relB);
    cudaGetSymbolAddress((void**)&hmid, g_hmid);
    cudaGetSymbolAddress((void**)&relmap, g_relmap);
    cudaGetSymbolAddress((void**)&wpk, g_wpack);
    cudaGetSymbolAddress((void**)&bia, g_bias);

    const size_t WB = (size_t)2 * CH * CH * 9;
    const size_t SB = (size_t)CH * HWSZ;

    // 0) pack + convert weights; combine biases
    pack_kernel<<<512, 256>>>(wpk + WP1, dmc_w + 0 * WB, 1152,
                              dmc_w + 2 * WB, 1152, 256);
    pack_kernel<<<512, 256>>>(wpk + WP2, imc_w01, 2304, imc_w23, 1152, 128);
    pack_kernel<<<512, 256>>>(wpk + WP3, rmc_w01, 2304, rmc_w23, 1152, 128);
    pack_kernel<<<512, 256>>>(wpk + WP4, dmc_w + 1 * WB, 1152,
                              dmc_w + 3 * WB, 1152, 256);
    pack_kernel<<<512, 256>>>(wpk + WP5, emb_w1, 2304, (const float*)0, 0, 128);
    pack_kernel<<<512, 256>>>(wpk + WP6, emb_w2, 1152, (const float*)0, 0, 128);

    bias_add<<<1, 256>>>(bia + 0 * 256, dmc_b + 0 * 256, dmc_b + 2 * 256, 256);
    bias_add<<<1, 128>>>(bia + 1 * 256, imc_b01, imc_b23, 128);
    bias_add<<<1, 128>>>(bia + 2 * 256, rmc_b01, rmc_b23, 128);
    bias_add<<<1, 256>>>(bia + 3 * 256, dmc_b + 1 * 256, dmc_b + 3 * 256, 256);
    bias_add<<<1, 128>>>(bia + 4 * 256, emb_b1, (const float*)0, 128);
    bias_add<<<1, 128>>>(bia + 5 * 256, emb_b2, (const float*)0, 128);

    // 1) rel embedding: two channel matmuls
    mm_kernel<<<dim3(CH, BATCH), NN>>>(tf,   rw1, rb1, hmid,   CINR, 1);
    mm_kernel<<<dim3(CH, BATCH), NN>>>(hmid, rw2, rb2, relmap, CH,   0);

    // 2) scatter interpolated rows into rel map
    scatter_kernel<<<dim3(HH, BATCH, 2), 64>>>(relmap, bbox, relA);

    // 3) TriGraph iteration 0 (dep never materialized; segments read directly)
    conv3(depB, img_in, relA, SB, SB,
          img_in, CH, relA, CH, nullptr, 0,
          wpk + WP1, bia + 0 * 256, 2 * CH, 0.5f, 1);
    conv3(imgA, img_in, nullptr, SB, 0,
          img_in, CH, relA, CH, relA, CH,
          wpk + WP2, bia + 1 * 256, CH, 0.5f, 1);
    conv3(relB, relA, nullptr, SB, 0,
          img_in, CH, relA, CH, img_in, CH,
          wpk + WP3, bia + 2 * 256, CH, 0.5f, 1);

    // 4) TriGraph iteration 1: only dep feeds the output
    conv3(depA, depB, depB + CH * HWSZ, 2 * SB, 2 * SB,
          imgA, CH, relB, CH, nullptr, 0,
          wpk + WP4, bia + 3 * 256, 2 * CH, 0.5f, 1);

    // 5) final embedding (imgA dead after step 4 -> reuse)
    conv3(imgA, nullptr, nullptr, 0, 0,
          depA, 2 * CH, nullptr, 0, nullptr, 0,
          wpk + WP5, bia + 4 * 256, CH, 1.f, 1);
    conv3(out, nullptr, nullptr, 0, 0,
          imgA, CH, nullptr, 0, nullptr, 0,
          wpk + WP6, bia + 5 * 256, CH, 1.f, 0);
}

// round 9
// speedup vs baseline: 1.4395x; 1.2199x over previous
#include <cuda_runtime.h>
#include <cuda_fp16.h>
#include <cstdint>

#define BATCH 4
#define CH    128
#define CINR  1024
#define NN    256
#define HH    120
#define WW    160
#define HWSZ  (HH*WW)

#define KC    32
#define CTA_M 128
#define CTA_N 128

// ---------------- scratch (device globals; no allocations allowed) ----------
__device__ __half g_h_img [BATCH*CH*HWSZ];
__device__ __half g_h_rel [BATCH*CH*HWSZ];
__device__ __half g_h_relB[BATCH*CH*HWSZ];
__device__ __half g_h_imgA[BATCH*CH*HWSZ];
__device__ __half g_h_depA[BATCH*2*CH*HWSZ];
__device__ __half g_h_depB[BATCH*2*CH*HWSZ];
__device__ float  g_hmid[BATCH*CH*NN];
__device__ float  g_relmap[BATCH*CH*NN];
__device__ __half g_wpack[2506752];
__device__ float  g_bias[6 * 256];

// pack-section offsets (halves)
#define WP1 0
#define WP2 589824
#define WP3 1032192
#define WP4 1474560
#define WP5 2064384
#define WP6 2359296

// ---------------- helpers ----------------------------------------------------
__device__ __forceinline__ void mma16(float* d, uint32_t a0, uint32_t a1,
                                      uint32_t a2, uint32_t a3,
                                      uint32_t b0, uint32_t b1){
    asm volatile(
        "mma.sync.aligned.m16n8k16.row.col.f32.f16.f16.f32 "
        "{%0,%1,%2,%3},{%4,%5,%6,%7},{%8,%9},{%0,%1,%2,%3};\n"
        : "+f"(d[0]), "+f"(d[1]), "+f"(d[2]), "+f"(d[3])
        : "r"(a0), "r"(a1), "r"(a2), "r"(a3), "r"(b0), "r"(b1));
}

// ---------------- weight pack: fp16 cvt + MMA layout + row XOR swizzle ------
__global__ void pack_kernel(__half* __restrict__ dst,
                            const float* __restrict__ W1, int K1,
                            const float* __restrict__ W2, int K2,
                            int Cout)
{
    const int Kt = K1 + K2;
    const int total = Cout * Kt;
    for (int idx = blockIdx.x * blockDim.x + threadIdx.x; idx < total;
         idx += gridDim.x * blockDim.x) {
        const int co = idx / Kt;
        const int kg = idx - co * Kt;
        float v = (kg < K1) ? W1[(size_t)co * K1 + kg]
                            : W2[(size_t)co * K2 + (kg - K1)];
        const int cb  = kg & ~31;
        const int w   = kg & 31;
        const int s   = w >> 4;
        const int kk  = w & 15;
        const int hi  = kk >> 3;
        const int c   = (kk & 7) >> 1;
        const int par = kk & 1;
        const int csw = c ^ (co & 3);
        dst[(size_t)co * Kt + cb + csw * 8 + s * 4 + hi * 2 + par] =
            __float2half_rn(v);
    }
}

// ---------------- fp32 -> fp16 convert --------------------------------------
__global__ void cvt_kernel(__half* __restrict__ dst, const float* __restrict__ src,
                           int n)
{
    for (int i = blockIdx.x * blockDim.x + threadIdx.x; i < n;
         i += gridDim.x * blockDim.x)
        dst[i] = __float2half_rn(src[i]);
}

// ---------------- 1x1 conv == channel matmul --------------------------------
__global__ void mm_kernel(const float* __restrict__ X, const float* __restrict__ Wm,
                          const float* __restrict__ bias, float* __restrict__ out,
                          int Cin, int do_relu)
{
    const int o = blockIdx.x;
    const int b = blockIdx.y;
    const int n = threadIdx.x;
    const float* xp = X + ((size_t)b * Cin) * NN + n;
    const float* wp = Wm + (size_t)o * Cin;
    float acc = bias[o];
    #pragma unroll 4
    for (int c = 0; c < Cin; ++c)
        acc = fmaf(wp[c], xp[(size_t)c * NN], acc);
    if (do_relu) acc = fmaxf(acc, 0.f);
    out[((size_t)b * CH + o) * NN + n] = acc;
}

// ---------------- box scatter of interpolated relation rows (fp16 out) ------
__global__ void scatter_kernel(const float* __restrict__ relmap,
                               const int* __restrict__ bbox,
                               __half* __restrict__ rel)
{
    __shared__ float row[64 * 161];
    const int y  = blockIdx.x;
    const int b  = blockIdx.y;
    const int c0 = blockIdx.z * 64;
    const int c  = threadIdx.x;

    float* myrow = row + c * 161;
    #pragma unroll
    for (int x = 0; x < 161; ++x) myrow[x] = 0.f;

    const float* rm = relmap + ((size_t)(b * CH + c0 + c)) * NN;

    for (int n = 0; n < NN; ++n) {
        const int* bb = bbox + ((size_t)b * NN + n) * 8;
        int sx1 = bb[0] >> 1, sy1 = bb[1] >> 1, sx2 = bb[2] >> 1, sy2 = bb[3] >> 1;
        int ox1 = bb[4] >> 1, oy1 = bb[5] >> 1, ox2 = bb[6] >> 1, oy2 = bb[7] >> 1;
        int sh = sy2 - sy1, sw = sx2 - sx1;
        int oh = oy2 - oy1, ow = ox2 - ox1;
        if (!(sh >= 5 && sw >= 5 && oh >= 5 && ow >= 5)) continue;

        if (y >= sy1 && y < sy2) {
            int s = (y - sy1) * 256 / sh;  s = min(s, 255);
            float v = rm[s];
            myrow[sx1] += v;
            myrow[sx2] -= v;
        }
        if (y >= oy1 && y < oy2) {
            int s = (y - oy1) * 256 / oh;  s = min(s, 255);
            float v = rm[s];
            myrow[ox1] += v;
            myrow[ox2] -= v;
        }
    }

    float run = 0.f;
    __half* op = rel + (((size_t)(b * CH + c0 + c)) * HH + y) * WW;
    #pragma unroll 4
    for (int x = 0; x < WW; ++x) { run += myrow[x]; op[x] = __float2half_rn(run); }
}

// ============ fp16 mma.sync implicit-GEMM 3-segment 3x3 SAME conv ===========
__global__ void __launch_bounds__(128, 2)
conv_mma(float* __restrict__ outF, __half* __restrict__ outH,
         const __half* __restrict__ baseLo, const __half* __restrict__ baseHi,
         size_t bsLo, size_t bsHi,
         const __half* __restrict__ X0, int C0,
         const __half* __restrict__ X1, int C1,
         const __half* __restrict__ X2, int C2,
         const __half* __restrict__ wp,
         const float* __restrict__ B1,
         int Cout, float scale, int do_relu)
{
    __shared__ __half sA[CTA_M * 32];
    __shared__ __half sB[CTA_N * 32];

    const int tid  = threadIdx.x;
    const int lane = tid & 31;
    const int wid  = tid >> 5;
    const int g    = lane >> 2;
    const int c    = lane & 3;
    const int wm   = wid >> 1;
    const int wn   = wid & 1;

    const int n0  = blockIdx.x * CTA_N;
    const int co0 = blockIdx.y * CTA_M;
    const int b   = blockIdx.z;
    const int Kt  = (C0 + C1 + C2) * 9;

    // A staging role: coalesced rows (swizzle already baked into packed gmem)
    const int arow  = tid >> 2;         // 0..31 (+32*jj)
    const int apart = tid & 3;          // 16B part within row

    // B staging role: fixed c-quad, pixels nbase + 32*j
    const int cs    = tid & 3;
    const int nbase = tid >> 2;

    int nfix[4];
    int vmask[4];
    #pragma unroll
    for (int j = 0; j < 4; ++j) {
        const int n = n0 + nbase + 32 * j;
        const int y = n / WW;
        const int x = n - y * WW;
        nfix[j]  = n - (WW + 1);
        vmask[j] = (y > 0) | ((y < HH - 1) << 1) | ((x > 0) << 2) | ((x < WW - 1) << 3);
    }

    const int fsw = (c ^ (g & 3)) * 8;

    float acc[4][8][4];
    #pragma unroll
    for (int mi = 0; mi < 4; ++mi)
        #pragma unroll
        for (int nj = 0; nj < 8; ++nj)
            #pragma unroll
            for (int t = 0; t < 4; ++t) acc[mi][nj][t] = 0.f;

    int gk = 0;
    #pragma unroll 1
    for (int seg = 0; seg < 3; ++seg) {
        const __half* X = (seg == 0) ? X0 : (seg == 1) ? X1 : X2;
        const int     C = (seg == 0) ? C0 : (seg == 1) ? C1 : C2;
        if (C == 0) continue;
        const unsigned short* Xb =
            (const unsigned short*)(X + (size_t)b * C * HWSZ);
        const int nch = (C * 9) >> 5;

        #pragma unroll 1
        for (int cc = 0; cc < nch; ++cc, ++gk) {
            const int k0 = cc * KC;
            const int wcol0 = gk * KC;
            __syncthreads();

            // ---- stage A: coalesced straight copy (swizzle in packed data) ----
            #pragma unroll
            for (int jj = 0; jj < 4; ++jj) {
                const int r = arow + jj * 32;
                const uint4 v = *(const uint4*)(wp + (size_t)(co0 + r) * Kt
                                                + wcol0 + apart * 8);
                *(uint4*)(sA + r * 32 + apart * 8) = v;
            }

            // ---- decode this thread's 8 k values ----
            int kb[8], req[8];
            #pragma unroll
            for (int m = 0; m < 8; ++m) {
                const int s   = m >> 2;
                const int hi  = (m >> 1) & 1;
                const int par = m & 1;
                const int k   = k0 + s * 16 + hi * 8 + 2 * cs + par;
                const int ci  = k / 9;
                const int tap = k - ci * 9;
                const int dy  = tap / 3;
                const int dx  = tap - dy * 3;
                kb[m]  = ci * HWSZ + dy * WW + dx;
                req[m] = (dy == 0 ? 1 : (dy == 2 ? 2 : 0)) |
                         (dx == 0 ? 4 : (dx == 2 ? 8 : 0));
            }

            // ---- stage B: fp16 gather -> STS.128 ----
            #pragma unroll
            for (int j = 0; j < 4; ++j) {
                const int n = nbase + 32 * j;
                unsigned int u[8];
                #pragma unroll
                for (int m = 0; m < 8; ++m) {
                    u[m] = 0;
                    if ((vmask[j] & req[m]) == req[m])
                        u[m] = Xb[kb[m] + nfix[j]];
                }
                uint4 v;
                v.x = u[0] | (u[1] << 16);
                v.y = u[2] | (u[3] << 16);
                v.z = u[4] | (u[5] << 16);
                v.w = u[6] | (u[7] << 16);
                const int csw = (cs ^ (n & 3)) * 8;
                *(uint4*)(sB + n * 32 + csw) = v;
            }
            __syncthreads();

            // ---- fragment loads (LDS.128 covers both k16 slices) ----
            uint4 alo[4], ahi[4], bfr[8];
            #pragma unroll
            for (int mi = 0; mi < 4; ++mi) {
                const int r = wm * 64 + mi * 16 + g;
                alo[mi] = *(const uint4*)(sA + r * 32 + fsw);
                ahi[mi] = *(const uint4*)(sA + (r + 8) * 32 + fsw);
            }
            #pragma unroll
            for (int nj = 0; nj < 8; ++nj) {
                const int r = wn * 64 + nj * 8 + g;
                bfr[nj] = *(const uint4*)(sB + r * 32 + fsw);
            }
            #pragma unroll
            for (int mi = 0; mi < 4; ++mi)
                #pragma unroll
                for (int nj = 0; nj < 8; ++nj)
                    mma16(acc[mi][nj], alo[mi].x, ahi[mi].x, alo[mi].y, ahi[mi].y,
                          bfr[nj].x, bfr[nj].y);
            #pragma unroll
            for (int mi = 0; mi < 4; ++mi)
                #pragma unroll
                for (int nj = 0; nj < 8; ++nj)
                    mma16(acc[mi][nj], alo[mi].z, ahi[mi].z, alo[mi].w, ahi[mi].w,
                          bfr[nj].z, bfr[nj].w);
        }
    }

    // ---- epilogue ----
    const __half* bp = (co0 == 0) ? baseLo : baseHi;
    const size_t bs = (co0 == 0) ? bsLo : bsHi;
    #pragma unroll
    for (int mi = 0; mi < 4; ++mi) {
        const int coa = co0 + wm * 64 + mi * 16 + g;
        const int cob = coa + 8;
        const float ba = B1[coa];
        const float bb = B1[cob];
        #pragma unroll
        for (int nj = 0; nj < 8; ++nj) {
            const int pix = n0 + wn * 64 + nj * 8 + 2 * c;
            const size_t oa = ((size_t)(b * Cout + coa)) * HWSZ + pix;
            const size_t ob = ((size_t)(b * Cout + cob)) * HWSZ + pix;
            float2 r0, r1;
            r0.x = acc[mi][nj][0] + ba;  r0.y = acc[mi][nj][1] + ba;
            r1.x = acc[mi][nj][2] + bb;  r1.y = acc[mi][nj][3] + bb;
            if (bp) {
                const size_t pa = b * bs + (size_t)(coa - co0) * HWSZ + pix;
                const size_t pb = b * bs + (size_t)(cob - co0) * HWSZ + pix;
                const float2 s0 = __half22float2(*(const __half2*)(bp + pa));
                const float2 s1 = __half22float2(*(const __half2*)(bp + pb));
                r0.x = fmaf(scale, r0.x, s0.x);  r0.y = fmaf(scale, r0.y, s0.y);
                r1.x = fmaf(scale, r1.x, s1.x);  r1.y = fmaf(scale, r1.y, s1.y);
            } else {
                r0.x *= scale; r0.y *= scale;
                r1.x *= scale; r1.y *= scale;
            }
            if (do_relu) {
                r0.x = fmaxf(r0.x, 0.f); r0.y = fmaxf(r0.y, 0.f);
                r1.x = fmaxf(r1.x, 0.f); r1.y = fmaxf(r1.y, 0.f);
            }
            if (outF) {
                *(float2*)(outF + oa) = r0;
                *(float2*)(outF + ob) = r1;
            } else {
                *(__half2*)(outH + oa) = __floats2half2_rn(r0.x, r0.y);
                *(__half2*)(outH + ob) = __floats2half2_rn(r1.x, r1.y);
            }
        }
    }
}

// ---------------- bias combine ----------------------------------------------
__global__ void bias_add(float* __restrict__ dst, const float* __restrict__ a,
                         const float* __restrict__ b, int n)
{
    int i = blockIdx.x * blockDim.x + threadIdx.x;
    if (i < n) dst[i] = a[i] + (b ? b[i] : 0.f);
}

static void conv3(float* outF, __half* outH,
                  const __half* baseLo, const __half* baseHi,
                  size_t bsLo, size_t bsHi,
                  const __half* X0, int C0, const __half* X1, int C1,
                  const __half* X2, int C2,
                  const __half* wp, const float* bias,
                  int Cout, float scale, int relu)
{
    dim3 g(HWSZ / CTA_N, Cout / CTA_M, BATCH);
    conv_mma<<<g, 128>>>(outF, outH, baseLo, baseHi, bsLo, bsHi,
                         X0, C0, X1, C1, X2, C2, wp, bias, Cout, scale, relu);
}

// ---------------------------------------------------------------------------
extern "C" void kernel_launch(void* const* d_in, const int* in_sizes, int n_in,
                              void* d_out, int out_size)
{
    const float* img_in  = (const float*)d_in[0];
    const float* tf      = (const float*)d_in[1];
    const float* rw1     = (const float*)d_in[2];
    const float* rb1     = (const float*)d_in[3];
    const float* rw2     = (const float*)d_in[4];
    const float* rb2     = (const float*)d_in[5];
    const float* dmc_w   = (const float*)d_in[6];
    const float* dmc_b   = (const float*)d_in[7];
    const float* imc_w01 = (const float*)d_in[8];
    const float* imc_b01 = (const float*)d_in[9];
    const float* imc_w23 = (const float*)d_in[10];
    const float* imc_b23 = (const float*)d_in[11];
    const float* rmc_w01 = (const float*)d_in[12];
    const float* rmc_b01 = (const float*)d_in[13];
    const float* rmc_w23 = (const float*)d_in[14];
    const float* rmc_b23 = (const float*)d_in[15];
    const float* emb_w1  = (const float*)d_in[16];
    const float* emb_b1  = (const float*)d_in[17];
    const float* emb_w2  = (const float*)d_in[18];
    const float* emb_b2  = (const float*)d_in[19];
    const int*   bbox    = (const int*)d_in[20];
    float* out = (float*)d_out;

    float *hmid, *relmap, *bia;
    __half *wpk, *hImg, *hRel, *hRelB, *hImgA, *hDepA, *hDepB;
    cudaGetSymbolAddress((void**)&hmid, g_hmid);
    cudaGetSymbolAddress((void**)&relmap, g_relmap);
    cudaGetSymbolAddress((void**)&wpk, g_wpack);
    cudaGetSymbolAddress((void**)&bia, g_bias);
    cudaGetSymbolAddress((void**)&hImg, g_h_img);
    cudaGetSymbolAddress((void**)&hRel, g_h_rel);
    cudaGetSymbolAddress((void**)&hRelB, g_h_relB);
    cudaGetSymbolAddress((void**)&hImgA, g_h_imgA);
    cudaGetSymbolAddress((void**)&hDepA, g_h_depA);
    cudaGetSymbolAddress((void**)&hDepB, g_h_depB);

    const size_t WB = (size_t)2 * CH * CH * 9;
    const size_t SB = (size_t)CH * HWSZ;

    // 0) pack weights, combine biases, convert img to fp16
    pack_kernel<<<512, 256>>>(wpk + WP1, dmc_w + 0 * WB, 1152,
                              dmc_w + 2 * WB, 1152, 256);
    pack_kernel<<<512, 256>>>(wpk + WP2, imc_w01, 2304, imc_w23, 1152, 128);
    pack_kernel<<<512, 256>>>(wpk + WP3, rmc_w01, 2304, rmc_w23, 1152, 128);
    pack_kernel<<<512, 256>>>(wpk + WP4, dmc_w + 1 * WB, 1152,
                              dmc_w + 3 * WB, 1152, 256);
    pack_kernel<<<512, 256>>>(wpk + WP5, emb_w1, 2304, (const float*)0, 0, 128);
    pack_kernel<<<512, 256>>>(wpk + WP6, emb_w2, 1152, (const float*)0, 0, 128);

    bias_add<<<1, 256>>>(bia + 0 * 256, dmc_b + 0 * 256, dmc_b + 2 * 256, 256);
    bias_add<<<1, 128>>>(bia + 1 * 256, imc_b01, imc_b23, 128);
    bias_add<<<1, 128>>>(bia + 2 * 256, rmc_b01, rmc_b23, 128);
    bias_add<<<1, 256>>>(bia + 3 * 256, dmc_b + 1 * 256, dmc_b + 3 * 256, 256);
    bias_add<<<1, 128>>>(bia + 4 * 256, emb_b1, (const float*)0, 128);
    bias_add<<<1, 128>>>(bia + 5 * 256, emb_b2, (const float*)0, 128);

    cvt_kernel<<<1024, 256>>>(hImg, img_in, BATCH * CH * HWSZ);

    // 1) rel embedding: two channel matmuls
    mm_kernel<<<dim3(CH, BATCH), NN>>>(tf,   rw1, rb1, hmid,   CINR, 1);
    mm_kernel<<<dim3(CH, BATCH), NN>>>(hmid, rw2, rb2, relmap, CH,   0);

    // 2) scatter interpolated rows into rel map (fp16 out)
    scatter_kernel<<<dim3(HH, BATCH, 2), 64>>>(relmap, bbox, hRel);

    // 3) TriGraph iteration 0
    conv3(nullptr, hDepB, hImg, hRel, SB, SB,
          hImg, CH, hRel, CH, nullptr, 0,
          wpk + WP1, bia + 0 * 256, 2 * CH, 0.5f, 1);
    conv3(nullptr, hImgA, hImg, nullptr, SB, 0,
          hImg, CH, hRel, CH, hRel, CH,
          wpk + WP2, bia + 1 * 256, CH, 0.5f, 1);
    conv3(nullptr, hRelB, hRel, nullptr, SB, 0,
          hImg, CH, hRel, CH, hImg, CH,
          wpk + WP3, bia + 2 * 256, CH, 0.5f, 1);

    // 4) TriGraph iteration 1: only dep feeds the output
    conv3(nullptr, hDepA, hDepB, hDepB + CH * HWSZ, 2 * SB, 2 * SB,
          hImgA, CH, hRelB, CH, nullptr, 0,
          wpk + WP4, bia + 3 * 256, 2 * CH, 0.5f, 1);

    // 5) final embedding (hImgA dead after step 4 -> reuse)
    conv3(nullptr, hImgA, nullptr, nullptr, 0, 0,
          hDepA, 2 * CH, nullptr, 0, nullptr, 0,
          wpk + WP5, bia + 4 * 256, CH, 1.f, 1);
    conv3(out, nullptr, nullptr, nullptr, 0, 0,
          hImgA, CH, nullptr, 0, nullptr, 0,
          wpk + WP6, bia + 5 * 256, CH, 1.f, 0);
}

// round 10
// speedup vs baseline: 1.4550x; 1.0108x over previous
#include <cuda_runtime.h>
#include <cuda_fp16.h>
#include <cstdint>

#define BATCH 4
#define CH    128
#define CINR  1024
#define NN    256
#define HH    120
#define WW    160
#define HWSZ  (HH*WW)

#define KC    32
#define CTA_M 128
#define CTA_N 128
#define SEGK  1152          // 128 ch * 9 taps
#define SEGCH 36            // chunks per 128-ch segment

// ---------------- scratch (device globals; no allocations allowed) ----------
__device__ __half g_h_img [BATCH*CH*HWSZ];
__device__ __half g_h_rel [BATCH*CH*HWSZ];
__device__ __half g_h_relB[BATCH*CH*HWSZ];
__device__ __half g_h_imgA[BATCH*CH*HWSZ];
__device__ __half g_h_depA[BATCH*2*CH*HWSZ];
__device__ __half g_h_depB[BATCH*2*CH*HWSZ];
__device__ float  g_hmid[BATCH*CH*NN];
__device__ float  g_relmap[BATCH*CH*NN];
__device__ __half g_wpack[2506752];
__device__ float  g_bias[6 * 256];
__device__ int2   g_desc[3 * SEGCH * 4 * 8];   // [gk][cs][m] -> {kb, req}

// pack-section offsets (halves)
#define WP1 0
#define WP2 589824
#define WP3 1032192
#define WP4 1474560
#define WP5 2064384
#define WP6 2359296

// ---------------- helpers ----------------------------------------------------
__device__ __forceinline__ void mma16(float* d, uint32_t a0, uint32_t a1,
                                      uint32_t a2, uint32_t a3,
                                      uint32_t b0, uint32_t b1){
    asm volatile(
        "mma.sync.aligned.m16n8k16.row.col.f32.f16.f16.f32 "
        "{%0,%1,%2,%3},{%4,%5,%6,%7},{%8,%9},{%0,%1,%2,%3};\n"
        : "+f"(d[0]), "+f"(d[1]), "+f"(d[2]), "+f"(d[3])
        : "r"(a0), "r"(a1), "r"(a2), "r"(a3), "r"(b0), "r"(b1));
}

// ---------------- weight pack: fp16 cvt + MMA layout + row XOR swizzle ------
__global__ void pack_kernel(__half* __restrict__ dst,
                            const float* __restrict__ W1, int K1,
                            const float* __restrict__ W2, int K2,
                            int Cout)
{
    const int Kt = K1 + K2;
    const int total = Cout * Kt;
    for (int idx = blockIdx.x * blockDim.x + threadIdx.x; idx < total;
         idx += gridDim.x * blockDim.x) {
        const int co = idx / Kt;
        const int kg = idx - co * Kt;
        float v = (kg < K1) ? W1[(size_t)co * K1 + kg]
                            : W2[(size_t)co * K2 + (kg - K1)];
        const int cb  = kg & ~31;
        const int w   = kg & 31;
        const int s   = w >> 4;
        const int kk  = w & 15;
        const int hi  = kk >> 3;
        const int c   = (kk & 7) >> 1;
        const int par = kk & 1;
        const int csw = c ^ (co & 3);
        dst[(size_t)co * Kt + cb + csw * 8 + s * 4 + hi * 2 + par] =
            __float2half_rn(v);
    }
}

// ---------------- gather-descriptor table -----------------------------------
__global__ void desc_kernel(int2* __restrict__ dst)
{
    const int idx = blockIdx.x * blockDim.x + threadIdx.x;
    if (idx >= 3 * SEGCH * 32) return;
    const int gk = idx >> 5;
    const int r  = idx & 31;
    const int cs = r >> 3;
    const int m  = r & 7;
    const int cc = gk % SEGCH;
    const int s   = m >> 2;
    const int hi  = (m >> 1) & 1;
    const int par = m & 1;
    const int k   = cc * KC + s * 16 + hi * 8 + 2 * cs + par;
    const int ci  = k / 9;
    const int tap = k - ci * 9;
    const int dy  = tap / 3;
    const int dx  = tap - dy * 3;
    const int kb  = ci * HWSZ + dy * WW + dx;
    const int req = (dy == 0 ? 1 : (dy == 2 ? 2 : 0)) |
                    (dx == 0 ? 4 : (dx == 2 ? 8 : 0));
    dst[(gk * 4 + cs) * 8 + m] = make_int2(kb, req);
}

// ---------------- fp32 -> fp16 convert --------------------------------------
__global__ void cvt_kernel(__half* __restrict__ dst, const float* __restrict__ src,
                           int n)
{
    for (int i = blockIdx.x * blockDim.x + threadIdx.x; i < n;
         i += gridDim.x * blockDim.x)
        dst[i] = __float2half_rn(src[i]);
}

// ---------------- 1x1 conv == channel matmul --------------------------------
__global__ void mm_kernel(const float* __restrict__ X, const float* __restrict__ Wm,
                          const float* __restrict__ bias, float* __restrict__ out,
                          int Cin, int do_relu)
{
    const int o = blockIdx.x;
    const int b = blockIdx.y;
    const int n = threadIdx.x;
    const float* xp = X + ((size_t)b * Cin) * NN + n;
    const float* wp = Wm + (size_t)o * Cin;
    float acc = bias[o];
    #pragma unroll 4
    for (int c = 0; c < Cin; ++c)
        acc = fmaf(wp[c], xp[(size_t)c * NN], acc);
    if (do_relu) acc = fmaxf(acc, 0.f);
    out[((size_t)b * CH + o) * NN + n] = acc;
}

// ---------------- box scatter of interpolated relation rows (fp16 out) ------
__global__ void scatter_kernel(const float* __restrict__ relmap,
                               const int* __restrict__ bbox,
                               __half* __restrict__ rel)
{
    __shared__ float row[64 * 161];
    const int y  = blockIdx.x;
    const int b  = blockIdx.y;
    const int c0 = blockIdx.z * 64;
    const int c  = threadIdx.x;

    float* myrow = row + c * 161;
    #pragma unroll
    for (int x = 0; x < 161; ++x) myrow[x] = 0.f;

    const float* rm = relmap + ((size_t)(b * CH + c0 + c)) * NN;

    for (int n = 0; n < NN; ++n) {
        const int* bb = bbox + ((size_t)b * NN + n) * 8;
        int sx1 = bb[0] >> 1, sy1 = bb[1] >> 1, sx2 = bb[2] >> 1, sy2 = bb[3] >> 1;
        int ox1 = bb[4] >> 1, oy1 = bb[5] >> 1, ox2 = bb[6] >> 1, oy2 = bb[7] >> 1;
        int sh = sy2 - sy1, sw = sx2 - sx1;
        int oh = oy2 - oy1, ow = ox2 - ox1;
        if (!(sh >= 5 && sw >= 5 && oh >= 5 && ow >= 5)) continue;

        if (y >= sy1 && y < sy2) {
            int s = (y - sy1) * 256 / sh;  s = min(s, 255);
            float v = rm[s];
            myrow[sx1] += v;
            myrow[sx2] -= v;
        }
        if (y >= oy1 && y < oy2) {
            int s = (y - oy1) * 256 / oh;  s = min(s, 255);
            float v = rm[s];
            myrow[ox1] += v;
            myrow[ox2] -= v;
        }
    }

    float run = 0.f;
    __half* op = rel + (((size_t)(b * CH + c0 + c)) * HH + y) * WW;
    #pragma unroll 4
    for (int x = 0; x < WW; ++x) { run += myrow[x]; op[x] = __float2half_rn(run); }
}

// ============ fp16 mma.sync implicit-GEMM multi-segment 3x3 SAME conv =======
// All segments are exactly 128 channels (36 chunks each), 1..3 segments.
__global__ void __launch_bounds__(128, 2)
conv_mma(float* __restrict__ outF, __half* __restrict__ outH,
         const __half* __restrict__ baseLo, const __half* __restrict__ baseHi,
         size_t bsLo, size_t bsHi,
         const __half* __restrict__ X0, size_t xs0,
         const __half* __restrict__ X1, size_t xs1,
         const __half* __restrict__ X2, size_t xs2,
         int nseg,
         const int2* __restrict__ desc,
         const __half* __restrict__ wp,
         const float* __restrict__ B1,
         int Cout, float scale, int do_relu)
{
    __shared__ __half sA[CTA_M * 32];
    __shared__ __half sB[CTA_N * 32];

    const int tid  = threadIdx.x;
    const int lane = tid & 31;
    const int wid  = tid >> 5;
    const int g    = lane >> 2;
    const int c    = lane & 3;
    const int wm   = wid >> 1;
    const int wn   = wid & 1;

    const int n0  = blockIdx.x * CTA_N;
    const int co0 = blockIdx.y * CTA_M;
    const int b   = blockIdx.z;
    const int Kt  = nseg * SEGK;

    // A staging role: coalesced rows (swizzle already baked into packed gmem)
    const int arow  = tid >> 2;
    const int apart = tid & 3;

    // B staging role: fixed c-quad, pixels nbase + 32*j
    const int cs    = tid & 3;
    const int nbase = tid >> 2;

    int nfix[4];
    int vmask[4];
    #pragma unroll
    for (int j = 0; j < 4; ++j) {
        const int n = n0 + nbase + 32 * j;
        const int y = n / WW;
        const int x = n - y * WW;
        nfix[j]  = n - (WW + 1);
        vmask[j] = (y > 0) | ((y < HH - 1) << 1) | ((x > 0) << 2) | ((x < WW - 1) << 3);
    }

    const int fsw = (c ^ (g & 3)) * 8;

    float acc[4][8][4];
    #pragma unroll
    for (int mi = 0; mi < 4; ++mi)
        #pragma unroll
        for (int nj = 0; nj < 8; ++nj)
            #pragma unroll
            for (int t = 0; t < 4; ++t) acc[mi][nj][t] = 0.f;

    int gk = 0;
    #pragma unroll 1
    for (int seg = 0; seg < nseg; ++seg) {
        const __half* Xs = (seg == 0) ? X0 : (seg == 1) ? X1 : X2;
        const size_t  xs = (seg == 0) ? xs0 : (seg == 1) ? xs1 : xs2;
        const unsigned short* Xb = (const unsigned short*)(Xs + (size_t)b * xs);

        #pragma unroll 1
        for (int cc = 0; cc < SEGCH; ++cc, ++gk) {
            // ---- gmem loads for this chunk: issue BEFORE the barrier ----
            uint4 av[4];
            #pragma unroll
            for (int jj = 0; jj < 4; ++jj) {
                const int r = arow + jj * 32;
                av[jj] = *(const uint4*)(wp + (size_t)(co0 + r) * Kt
                                         + gk * KC + apart * 8);
            }
            const uint4* dq = (const uint4*)(desc + ((size_t)(gk * 4 + cs)) * 8);
            const uint4 e0 = __ldg(dq + 0);
            const uint4 e1 = __ldg(dq + 1);
            const uint4 e2 = __ldg(dq + 2);
            const uint4 e3 = __ldg(dq + 3);

            __syncthreads();

            // ---- stage A ----
            #pragma unroll
            for (int jj = 0; jj < 4; ++jj) {
                const int r = arow + jj * 32;
                *(uint4*)(sA + r * 32 + apart * 8) = av[jj];
            }

            // ---- stage B: descriptor-driven fp16 gather -> STS.128 ----
            const int kb[8]  = {(int)e0.x, (int)e0.z, (int)e1.x, (int)e1.z,
                                (int)e2.x, (int)e2.z, (int)e3.x, (int)e3.z};
            const int req[8] = {(int)e0.y, (int)e0.w, (int)e1.y, (int)e1.w,
                                (int)e2.y, (int)e2.w, (int)e3.y, (int)e3.w};
            #pragma unroll
            for (int j = 0; j < 4; ++j) {
                const int n = nbase + 32 * j;
                unsigned int u[8];
                #pragma unroll
                for (int m = 0; m < 8; ++m) {
                    u[m] = 0;
                    if ((vmask[j] & req[m]) == req[m])
                        u[m] = Xb[kb[m] + nfix[j]];
                }
                uint4 v;
                v.x = u[0] | (u[1] << 16);
                v.y = u[2] | (u[3] << 16);
                v.z = u[4] | (u[5] << 16);
                v.w = u[6] | (u[7] << 16);
                const int csw = (cs ^ (n & 3)) * 8;
                *(uint4*)(sB + n * 32 + csw) = v;
            }
            __syncthreads();

            // ---- fragment loads (LDS.128 covers both k16 slices) ----
            uint4 alo[4], ahi[4], bfr[8];
            #pragma unroll
            for (int mi = 0; mi < 4; ++mi) {
                const int r = wm * 64 + mi * 16 + g;
                alo[mi] = *(const uint4*)(sA + r * 32 + fsw);
                ahi[mi] = *(const uint4*)(sA + (r + 8) * 32 + fsw);
            }
            #pragma unroll
            for (int nj = 0; nj < 8; ++nj) {
                const int r = wn * 64 + nj * 8 + g;
                bfr[nj] = *(const uint4*)(sB + r * 32 + fsw);
            }
            #pragma unroll
            for (int mi = 0; mi < 4; ++mi)
                #pragma unroll
                for (int nj = 0; nj < 8; ++nj)
                    mma16(acc[mi][nj], alo[mi].x, ahi[mi].x, alo[mi].y, ahi[mi].y,
                          bfr[nj].x, bfr[nj].y);
            #pragma unroll
            for (int mi = 0; mi < 4; ++mi)
                #pragma unroll
                for (int nj = 0; nj < 8; ++nj)
                    mma16(acc[mi][nj], alo[mi].z, ahi[mi].z, alo[mi].w, ahi[mi].w,
                          bfr[nj].z, bfr[nj].w);
        }
    }

    // ---- epilogue ----
    const __half* bp = (co0 == 0) ? baseLo : baseHi;
    const size_t bs = (co0 == 0) ? bsLo : bsHi;
    #pragma unroll
    for (int mi = 0; mi < 4; ++mi) {
        const int coa = co0 + wm * 64 + mi * 16 + g;
        const int cob = coa + 8;
        const float ba = B1[coa];
        const float bb = B1[cob];
        #pragma unroll
        for (int nj = 0; nj < 8; ++nj) {
            const int pix = n0 + wn * 64 + nj * 8 + 2 * c;
            const size_t oa = ((size_t)(b * Cout + coa)) * HWSZ + pix;
            const size_t ob = ((size_t)(b * Cout + cob)) * HWSZ + pix;
            float2 r0, r1;
            r0.x = acc[mi][nj][0] + ba;  r0.y = acc[mi][nj][1] + ba;
            r1.x = acc[mi][nj][2] + bb;  r1.y = acc[mi][nj][3] + bb;
            if (bp) {
                const size_t pa = b * bs + (size_t)(coa - co0) * HWSZ + pix;
                const size_t pb = b * bs + (size_t)(cob - co0) * HWSZ + pix;
                const float2 s0 = __half22float2(*(const __half2*)(bp + pa));
                const float2 s1 = __half22float2(*(const __half2*)(bp + pb));
                r0.x = fmaf(scale, r0.x, s0.x);  r0.y = fmaf(scale, r0.y, s0.y);
                r1.x = fmaf(scale, r1.x, s1.x);  r1.y = fmaf(scale, r1.y, s1.y);
            } else {
                r0.x *= scale; r0.y *= scale;
                r1.x *= scale; r1.y *= scale;
            }
            if (do_relu) {
                r0.x = fmaxf(r0.x, 0.f); r0.y = fmaxf(r0.y, 0.f);
                r1.x = fmaxf(r1.x, 0.f); r1.y = fmaxf(r1.y, 0.f);
            }
            if (outF) {
                *(float2*)(outF + oa) = r0;
                *(float2*)(outF + ob) = r1;
            } else {
                *(__half2*)(outH + oa) = __floats2half2_rn(r0.x, r0.y);
                *(__half2*)(outH + ob) = __floats2half2_rn(r1.x, r1.y);
            }
        }
    }
}

// ---------------- bias combine ----------------------------------------------
__global__ void bias_add(float* __restrict__ dst, const float* __restrict__ a,
                         const float* __restrict__ b, int n)
{
    int i = blockIdx.x * blockDim.x + threadIdx.x;
    if (i < n) dst[i] = a[i] + (b ? b[i] : 0.f);
}

// ---------------------------------------------------------------------------
extern "C" void kernel_launch(void* const* d_in, const int* in_sizes, int n_in,
                              void* d_out, int out_size)
{
    const float* img_in  = (const float*)d_in[0];
    const float* tf      = (const float*)d_in[1];
    const float* rw1     = (const float*)d_in[2];
    const float* rb1     = (const float*)d_in[3];
    const float* rw2     = (const float*)d_in[4];
    const float* rb2     = (const float*)d_in[5];
    const float* dmc_w   = (const float*)d_in[6];
    const float* dmc_b   = (const float*)d_in[7];
    const float* imc_w01 = (const float*)d_in[8];
    const float* imc_b01 = (const float*)d_in[9];
    const float* imc_w23 = (const float*)d_in[10];
    const float* imc_b23 = (const float*)d_in[11];
    const float* rmc_w01 = (const float*)d_in[12];
    const float* rmc_b01 = (const float*)d_in[13];
    const float* rmc_w23 = (const float*)d_in[14];
    const float* rmc_b23 = (const float*)d_in[15];
    const float* emb_w1  = (const float*)d_in[16];
    const float* emb_b1  = (const float*)d_in[17];
    const float* emb_w2  = (const float*)d_in[18];
    const float* emb_b2  = (const float*)d_in[19];
    const int*   bbox    = (const int*)d_in[20];
    float* out = (float*)d_out;

    float *hmid, *relmap, *bia;
    __half *wpk, *hImg, *hRel, *hRelB, *hImgA, *hDepA, *hDepB;
    int2* dsc;
    cudaGetSymbolAddress((void**)&hmid, g_hmid);
    cudaGetSymbolAddress((void**)&relmap, g_relmap);
    cudaGetSymbolAddress((void**)&wpk, g_wpack);
    cudaGetSymbolAddress((void**)&bia, g_bias);
    cudaGetSymbolAddress((void**)&hImg, g_h_img);
    cudaGetSymbolAddress((void**)&hRel, g_h_rel);
    cudaGetSymbolAddress((void**)&hRelB, g_h_relB);
    cudaGetSymbolAddress((void**)&hImgA, g_h_imgA);
    cudaGetSymbolAddress((void**)&hDepA, g_h_depA);
    cudaGetSymbolAddress((void**)&hDepB, g_h_depB);
    cudaGetSymbolAddress((void**)&dsc, g_desc);

    const size_t WB = (size_t)2 * CH * CH * 9;
    const size_t SB = (size_t)CH * HWSZ;

    // 0) pack weights, descriptor table, biases, img fp16
    pack_kernel<<<512, 256>>>(wpk + WP1, dmc_w + 0 * WB, 1152,
                              dmc_w + 2 * WB, 1152, 256);
    pack_kernel<<<512, 256>>>(wpk + WP2, imc_w01, 2304, imc_w23, 1152, 128);
    pack_kernel<<<512, 256>>>(wpk + WP3, rmc_w01, 2304, rmc_w23, 1152, 128);
    pack_kernel<<<512, 256>>>(wpk + WP4, dmc_w + 1 * WB, 1152,
                              dmc_w + 3 * WB, 1152, 256);
    pack_kernel<<<512, 256>>>(wpk + WP5, emb_w1, 2304, (const float*)0, 0, 128);
    pack_kernel<<<512, 256>>>(wpk + WP6, emb_w2, 1152, (const float*)0, 0, 128);
    desc_kernel<<<(3 * SEGCH * 32 + 255) / 256, 256>>>(dsc);

    bias_add<<<1, 256>>>(bia + 0 * 256, dmc_b + 0 * 256, dmc_b + 2 * 256, 256);
    bias_add<<<1, 128>>>(bia + 1 * 256, imc_b01, imc_b23, 128);
    bias_add<<<1, 128>>>(bia + 2 * 256, rmc_b01, rmc_b23, 128);
    bias_add<<<1, 256>>>(bia + 3 * 256, dmc_b + 1 * 256, dmc_b + 3 * 256, 256);
    bias_add<<<1, 128>>>(bia + 4 * 256, emb_b1, (const float*)0, 128);
    bias_add<<<1, 128>>>(bia + 5 * 256, emb_b2, (const float*)0, 128);

    cvt_kernel<<<1024, 256>>>(hImg, img_in, BATCH * CH * HWSZ);

    // 1) rel embedding
    mm_kernel<<<dim3(CH, BATCH), NN>>>(tf,   rw1, rb1, hmid,   CINR, 1);
    mm_kernel<<<dim3(CH, BATCH), NN>>>(hmid, rw2, rb2, relmap, CH,   0);

    // 2) scatter interpolated rows into rel map (fp16 out)
    scatter_kernel<<<dim3(HH, BATCH, 2), 64>>>(relmap, bbox, hRel);

    dim3 g2(HWSZ / CTA_N, 2, BATCH);   // Cout = 256
    dim3 g1(HWSZ / CTA_N, 1, BATCH);   // Cout = 128

    // 3) TriGraph iteration 0
    conv_mma<<<g2, 128>>>(nullptr, hDepB, hImg, hRel, SB, SB,
                          hImg, SB, hRel, SB, nullptr, 0, 2,
                          dsc, wpk + WP1, bia + 0 * 256, 256, 0.5f, 1);
    conv_mma<<<g1, 128>>>(nullptr, hImgA, hImg, nullptr, SB, 0,
                          hImg, SB, hRel, SB, hRel, SB, 3,
                          dsc, wpk + WP2, bia + 1 * 256, 128, 0.5f, 1);
    conv_mma<<<g1, 128>>>(nullptr, hRelB, hRel, nullptr, SB, 0,
                          hImg, SB, hRel, SB, hImg, SB, 3,
                          dsc, wpk + WP3, bia + 2 * 256, 128, 0.5f, 1);

    // 4) TriGraph iteration 1: only dep feeds the output
    conv_mma<<<g2, 128>>>(nullptr, hDepA, hDepB, hDepB + CH * HWSZ,
                          2 * SB, 2 * SB,
                          hImgA, SB, hRelB, SB, nullptr, 0, 2,
                          dsc, wpk + WP4, bia + 3 * 256, 256, 0.5f, 1);

    // 5) final embedding (hImgA dead after step 4 -> reuse); dep split 2 segs
    conv_mma<<<g1, 128>>>(nullptr, hImgA, nullptr, nullptr, 0, 0,
                          hDepA, 2 * SB, hDepA + SB, 2 * SB, nullptr, 0, 2,
                          dsc, wpk + WP5, bia + 4 * 256, 128, 1.f, 1);
    conv_mma<<<g1, 128>>>(out, nullptr, nullptr, nullptr, 0, 0,
                          hImgA, SB, nullptr, 0, nullptr, 0, 1,
                          dsc, wpk + WP6, bia + 5 * 256, 128, 1.f, 0);
}

// round 15
// speedup vs baseline: 1.5253x; 1.0483x over previous
#include <cuda_runtime.h>
#include <cuda_fp16.h>
#include <cstdint>

#define BATCH 4
#define CH    128
#define CINR  1024
#define NN    256
#define HH    120
#define WW    160
#define HWSZ  (HH*WW)

#define KC    32
#define CTA_M 128
#define CTA_N 128
#define SEGK  1152          // 128 ch * 9 taps
#define SEGCH 36            // chunks per 128-ch segment

// ---------------- scratch (device globals; no allocations allowed) ----------
__device__ __half g_h_img [BATCH*CH*HWSZ];
__device__ __half g_h_rel [BATCH*CH*HWSZ];
__device__ __half g_h_relB[BATCH*CH*HWSZ];
__device__ __half g_h_imgA[BATCH*CH*HWSZ];
__device__ __half g_h_depA[BATCH*2*CH*HWSZ];
__device__ __half g_h_depB[BATCH*2*CH*HWSZ];
__device__ float  g_hmid[BATCH*CH*NN];
__device__ float  g_relmap[BATCH*CH*NN];
__device__ __half g_wpack[2506752];
__device__ float  g_bias[6 * 256];
__device__ int2   g_desc[3 * SEGCH * 4 * 8];   // [gk][cs][m] -> {kb, req}

// pack-section offsets (halves)
#define WP1 0
#define WP2 589824
#define WP3 1032192
#define WP4 1474560
#define WP5 2064384
#define WP6 2359296

// ---------------- helpers ----------------------------------------------------
__device__ __forceinline__ void mma16(float* d, uint32_t a0, uint32_t a1,
                                      uint32_t a2, uint32_t a3,
                                      uint32_t b0, uint32_t b1){
    asm volatile(
        "mma.sync.aligned.m16n8k16.row.col.f32.f16.f16.f32 "
        "{%0,%1,%2,%3},{%4,%5,%6,%7},{%8,%9},{%0,%1,%2,%3};\n"
        : "+f"(d[0]), "+f"(d[1]), "+f"(d[2]), "+f"(d[3])
        : "r"(a0), "r"(a1), "r"(a2), "r"(a3), "r"(b0), "r"(b1));
}

// ---------------- weight pack: fp16 cvt + [chunk][co][32] + col permutation --
__global__ void pack_kernel(__half* __restrict__ dst,
                            const float* __restrict__ W1, int K1,
                            const float* __restrict__ W2, int K2,
                            int Cout)
{
    const int Kt = K1 + K2;
    const int total = Cout * Kt;
    for (int idx = blockIdx.x * blockDim.x + threadIdx.x; idx < total;
         idx += gridDim.x * blockDim.x) {
        const int co = idx / Kt;
        const int kg = idx - co * Kt;
        float v = (kg < K1) ? W1[(size_t)co * K1 + kg]
                            : W2[(size_t)co * K2 + (kg - K1)];
        const int gk  = kg >> 5;
        const int w   = kg & 31;
        const int s   = w >> 4;
        const int kk  = w & 15;
        const int hi  = kk >> 3;
        const int c   = (kk & 7) >> 1;
        const int par = kk & 1;
        const int csw = c ^ (co & 3);
        dst[((size_t)gk * Cout + co) * 32 + csw * 8 + s * 4 + hi * 2 + par] =
            __float2half_rn(v);
    }
}

// ---------------- gather-descriptor table -----------------------------------
__global__ void desc_kernel(int2* __restrict__ dst)
{
    const int idx = blockIdx.x * blockDim.x + threadIdx.x;
    if (idx >= 3 * SEGCH * 32) return;
    const int gk = idx >> 5;
    const int r  = idx & 31;
    const int cs = r >> 3;
    const int m  = r & 7;
    const int cc = gk % SEGCH;
    const int s   = m >> 2;
    const int hi  = (m >> 1) & 1;
    const int par = m & 1;
    const int k   = cc * KC + s * 16 + hi * 8 + 2 * cs + par;
    const int ci  = k / 9;
    const int tap = k - ci * 9;
    const int dy  = tap / 3;
    const int dx  = tap - dy * 3;
    const int kb  = ci * HWSZ + dy * WW + dx;
    const int req = (dy == 0 ? 1 : (dy == 2 ? 2 : 0)) |
                    (dx == 0 ? 4 : (dx == 2 ? 8 : 0));
    dst[(gk * 4 + cs) * 8 + m] = make_int2(kb, req);
}

// ---------------- fp32 -> fp16 convert --------------------------------------
__global__ void cvt_kernel(__half* __restrict__ dst, const float* __restrict__ src,
                           int n)
{
    for (int i = blockIdx.x * blockDim.x + threadIdx.x; i < n;
         i += gridDim.x * blockDim.x)
        dst[i] = __float2half_rn(src[i]);
}

// ---------------- 1x1 conv == channel matmul --------------------------------
__global__ void mm_kernel(const float* __restrict__ X, const float* __restrict__ Wm,
                          const float* __restrict__ bias, float* __restrict__ out,
                          int Cin, int do_relu)
{
    const int o = blockIdx.x;
    const int b = blockIdx.y;
    const int n = threadIdx.x;
    const float* xp = X + ((size_t)b * Cin) * NN + n;
    const float* wp = Wm + (size_t)o * Cin;
    float acc = bias[o];
    #pragma unroll 4
    for (int c = 0; c < Cin; ++c)
        acc = fmaf(wp[c], xp[(size_t)c * NN], acc);
    if (do_relu) acc = fmaxf(acc, 0.f);
    out[((size_t)b * CH + o) * NN + n] = acc;
}

// ---------------- box scatter of interpolated relation rows (fp16 out) ------
__global__ void scatter_kernel(const float* __restrict__ relmap,
                               const int* __restrict__ bbox,
                               __half* __restrict__ rel)
{
    __shared__ float row[64 * 161];
    const int y  = blockIdx.x;
    const int b  = blockIdx.y;
    const int c0 = blockIdx.z * 64;
    const int c  = threadIdx.x;

    float* myrow = row + c * 161;
    #pragma unroll
    for (int x = 0; x < 161; ++x) myrow[x] = 0.f;

    const float* rm = relmap + ((size_t)(b * CH + c0 + c)) * NN;

    for (int n = 0; n < NN; ++n) {
        const int* bb = bbox + ((size_t)b * NN + n) * 8;
        int sx1 = bb[0] >> 1, sy1 = bb[1] >> 1, sx2 = bb[2] >> 1, sy2 = bb[3] >> 1;
        int ox1 = bb[4] >> 1, oy1 = bb[5] >> 1, ox2 = bb[6] >> 1, oy2 = bb[7] >> 1;
        int sh = sy2 - sy1, sw = sx2 - sx1;
        int oh = oy2 - oy1, ow = ox2 - ox1;
        if (!(sh >= 5 && sw >= 5 && oh >= 5 && ow >= 5)) continue;

        if (y >= sy1 && y < sy2) {
            int s = (y - sy1) * 256 / sh;  s = min(s, 255);
            float v = rm[s];
            myrow[sx1] += v;
            myrow[sx2] -= v;
        }
        if (y >= oy1 && y < oy2) {
            int s = (y - oy1) * 256 / oh;  s = min(s, 255);
            float v = rm[s];
            myrow[ox1] += v;
            myrow[ox2] -= v;
        }
    }

    float run = 0.f;
    __half* op = rel + (((size_t)(b * CH + c0 + c)) * HH + y) * WW;
    #pragma unroll 4
    for (int x = 0; x < WW; ++x) { run += myrow[x]; op[x] = __float2half_rn(run); }
}

// ============ fp16 mma.sync implicit-GEMM multi-segment 3x3 SAME conv =======
// Double-buffered smem; chunk gk+1 gmem loads overlap chunk gk MMA phase.
__global__ void __launch_bounds__(128, 2)
conv_mma(float* __restrict__ outF, __half* __restrict__ outH,
         const __half* __restrict__ baseLo, const __half* __restrict__ baseHi,
         size_t bsLo, size_t bsHi,
         const __half* __restrict__ X0, size_t xs0,
         const __half* __restrict__ X1, size_t xs1,
         const __half* __restrict__ X2, size_t xs2,
         int nseg,
         const int2* __restrict__ desc,
         const __half* __restrict__ wp,
         const float* __restrict__ B1,
         int Cout, float scale, int do_relu)
{
    __shared__ __half sA[2][CTA_M * 32];
    __shared__ __half sB[2][CTA_N * 32];

    const int tid  = threadIdx.x;
    const int lane = tid & 31;
    const int wid  = tid >> 5;
    const int g    = lane >> 2;
    const int c    = lane & 3;
    const int wm   = wid >> 1;
    const int wn   = wid & 1;

    const int n0  = blockIdx.x * CTA_N;
    const int co0 = blockIdx.y * CTA_M;
    const int b   = blockIdx.z;
    const int nch = nseg * SEGCH;

    const int arow  = tid >> 2;
    const int apart = tid & 3;
    const int cs    = tid & 3;
    const int nbase = tid >> 2;

    const unsigned short* Xb0 = (const unsigned short*)(X0 + (size_t)b * xs0);
    const unsigned short* Xb1 = X1 ? (const unsigned short*)(X1 + (size_t)b * xs1) : Xb0;
    const unsigned short* Xb2 = X2 ? (const unsigned short*)(X2 + (size_t)b * xs2) : Xb0;

    int nfix[4];
    int vmask[4];
    #pragma unroll
    for (int j = 0; j < 4; ++j) {
        const int n = n0 + nbase + 32 * j;
        const int y = n / WW;
        const int x = n - y * WW;
        nfix[j]  = n - (WW + 1);
        vmask[j] = (y > 0) | ((y < HH - 1) << 1) | ((x > 0) << 2) | ((x < WW - 1) << 3);
    }

    const int fsw = (c ^ (g & 3)) * 8;
    const int bsw = (cs ^ (nbase & 3)) * 8;   // store swizzle (n&3 == nbase&3)

    float acc[4][8][4];
    #pragma unroll
    for (int mi = 0; mi < 4; ++mi)
        #pragma unroll
        for (int nj = 0; nj < 8; ++nj)
            #pragma unroll
            for (int t = 0; t < 4; ++t) acc[mi][nj][t] = 0.f;

    uint4 avC[4], bvC[4], avN[4], bvN[4];

    // ---- chunk loader (A + desc + gather into registers) ----
    auto load_chunk = [&](int gk, uint4* av, uint4* bv) {
        #pragma unroll
        for (int jj = 0; jj < 4; ++jj) {
            const int r = arow + jj * 32;
            av[jj] = *(const uint4*)(wp + ((size_t)gk * Cout + co0 + r) * 32
                                     + apart * 8);
        }
        const uint4* dq = (const uint4*)(desc + ((size_t)(gk * 4 + cs)) * 8);
        const uint4 e0 = __ldg(dq + 0);
        const uint4 e1 = __ldg(dq + 1);
        const uint4 e2 = __ldg(dq + 2);
        const uint4 e3 = __ldg(dq + 3);
        const int kb[8]  = {(int)e0.x, (int)e0.z, (int)e1.x, (int)e1.z,
                            (int)e2.x, (int)e2.z, (int)e3.x, (int)e3.z};
        const int req[8] = {(int)e0.y, (int)e0.w, (int)e1.y, (int)e1.w,
                            (int)e2.y, (int)e2.w, (int)e3.y, (int)e3.w};
        const unsigned short* Xb = (gk < SEGCH) ? Xb0
                                  : (gk < 2 * SEGCH) ? Xb1 : Xb2;
        #pragma unroll
        for (int j = 0; j < 4; ++j) {
            unsigned int u[8];
            #pragma unroll
            for (int m = 0; m < 8; ++m) {
                u[m] = 0;
                if ((vmask[j] & req[m]) == req[m])
                    u[m] = Xb[kb[m] + nfix[j]];
            }
            bv[j].x = u[0] | (u[1] << 16);
            bv[j].y = u[2] | (u[3] << 16);
            bv[j].z = u[4] | (u[5] << 16);
            bv[j].w = u[6] | (u[7] << 16);
        }
    };

    load_chunk(0, avC, bvC);

    #pragma unroll 1
    for (int gk = 0; gk < nch; ++gk) {
        const int buf = gk & 1;
        __half* pA = sA[buf];
        __half* pB = sB[buf];

        // ---- stage chunk gk from registers ----
        #pragma unroll
        for (int jj = 0; jj < 4; ++jj) {
            const int r = arow + jj * 32;
            *(uint4*)(pA + r * 32 + apart * 8) = avC[jj];
        }
        #pragma unroll
        for (int j = 0; j < 4; ++j)
            *(uint4*)(pB + (nbase + 32 * j) * 32 + bsw) = bvC[j];

        // ---- prefetch chunk gk+1 (latency hides under MMA below) ----
        if (gk + 1 < nch)
            load_chunk(gk + 1, avN, bvN);

        __syncthreads();

        // ---- MMA phase on buf ----
        uint4 alo[4], ahi[4], bfr[8];
        #pragma unroll
        for (int mi = 0; mi < 4; ++mi) {
            const int r = wm * 64 + mi * 16 + g;
            alo[mi] = *(const uint4*)(pA + r * 32 + fsw);
            ahi[mi] = *(const uint4*)(pA + (r + 8) * 32 + fsw);
        }
        #pragma unroll
        for (int nj = 0; nj < 8; ++nj) {
            const int r = wn * 64 + nj * 8 + g;
            bfr[nj] = *(const uint4*)(pB + r * 32 + fsw);
        }
        #pragma unroll
        for (int mi = 0; mi < 4; ++mi)
            #pragma unroll
            for (int nj = 0; nj < 8; ++nj)
                mma16(acc[mi][nj], alo[mi].x, ahi[mi].x, alo[mi].y, ahi[mi].y,
                      bfr[nj].x, bfr[nj].y);
        #pragma unroll
        for (int mi = 0; mi < 4; ++mi)
            #pragma unroll
            for (int nj = 0; nj < 8; ++nj)
                mma16(acc[mi][nj], alo[mi].z, ahi[mi].z, alo[mi].w, ahi[mi].w,
                      bfr[nj].z, bfr[nj].w);

        // ---- rotate staging registers ----
        #pragma unroll
        for (int i = 0; i < 4; ++i) { avC[i] = avN[i]; bvC[i] = bvN[i]; }
    }

    // ---- epilogue ----
    const __half* bp = (co0 == 0) ? baseLo : baseHi;
    const size_t bs = (co0 == 0) ? bsLo : bsHi;
    #pragma unroll
    for (int mi = 0; mi < 4; ++mi) {
        const int coa = co0 + wm * 64 + mi * 16 + g;
        const int cob = coa + 8;
        const float ba = B1[coa];
        const float bb = B1[cob];
        #pragma unroll
        for (int nj = 0; nj < 8; ++nj) {
            const int pix = n0 + wn * 64 + nj * 8 + 2 * c;
            const size_t oa = ((size_t)(b * Cout + coa)) * HWSZ + pix;
            const size_t ob = ((size_t)(b * Cout + cob)) * HWSZ + pix;
            float2 r0, r1;
            r0.x = acc[mi][nj][0] + ba;  r0.y = acc[mi][nj][1] + ba;
            r1.x = acc[mi][nj][2] + bb;  r1.y = acc[mi][nj][3] + bb;
            if (bp) {
                const size_t pa = b * bs + (size_t)(coa - co0) * HWSZ + pix;
                const size_t pb = b * bs + (size_t)(cob - co0) * HWSZ + pix;
                const float2 s0 = __half22float2(*(const __half2*)(bp + pa));
                const float2 s1 = __half22float2(*(const __half2*)(bp + pb));
                r0.x = fmaf(scale, r0.x, s0.x);  r0.y = fmaf(scale, r0.y, s0.y);
                r1.x = fmaf(scale, r1.x, s1.x);  r1.y = fmaf(scale, r1.y, s1.y);
            } else {
                r0.x *= scale; r0.y *= scale;
                r1.x *= scale; r1.y *= scale;
            }
            if (do_relu) {
                r0.x = fmaxf(r0.x, 0.f); r0.y = fmaxf(r0.y, 0.f);
                r1.x = fmaxf(r1.x, 0.f); r1.y = fmaxf(r1.y, 0.f);
            }
            if (outF) {
                *(float2*)(outF + oa) = r0;
                *(float2*)(outF + ob) = r1;
            } else {
                *(__half2*)(outH + oa) = __floats2half2_rn(r0.x, r0.y);
                *(__half2*)(outH + ob) = __floats2half2_rn(r1.x, r1.y);
            }
        }
    }
}

// ---------------- bias combine ----------------------------------------------
__global__ void bias_add(float* __restrict__ dst, const float* __restrict__ a,
                         const float* __restrict__ b, int n)
{
    int i = blockIdx.x * blockDim.x + threadIdx.x;
    if (i < n) dst[i] = a[i] + (b ? b[i] : 0.f);
}

// ---------------------------------------------------------------------------
extern "C" void kernel_launch(void* const* d_in, const int* in_sizes, int n_in,
                              void* d_out, int out_size)
{
    const float* img_in  = (const float*)d_in[0];
    const float* tf      = (const float*)d_in[1];
    const float* rw1     = (const float*)d_in[2];
    const float* rb1     = (const float*)d_in[3];
    const float* rw2     = (const float*)d_in[4];
    const float* rb2     = (const float*)d_in[5];
    const float* dmc_w   = (const float*)d_in[6];
    const float* dmc_b   = (const float*)d_in[7];
    const float* imc_w01 = (const float*)d_in[8];
    const float* imc_b01 = (const float*)d_in[9];
    const float* imc_w23 = (const float*)d_in[10];
    const float* imc_b23 = (const float*)d_in[11];
    const float* rmc_w01 = (const float*)d_in[12];
    const float* rmc_b01 = (const float*)d_in[13];
    const float* rmc_w23 = (const float*)d_in[14];
    const float* rmc_b23 = (const float*)d_in[15];
    const float* emb_w1  = (const float*)d_in[16];
    const float* emb_b1  = (const float*)d_in[17];
    const float* emb_w2  = (const float*)d_in[18];
    const float* emb_b2  = (const float*)d_in[19];
    const int*   bbox    = (const int*)d_in[20];
    float* out = (float*)d_out;

    float *hmid, *relmap, *bia;
    __half *wpk, *hImg, *hRel, *hRelB, *hImgA, *hDepA, *hDepB;
    int2* dsc;
    cudaGetSymbolAddress((void**)&hmid, g_hmid);
    cudaGetSymbolAddress((void**)&relmap, g_relmap);
    cudaGetSymbolAddress((void**)&wpk, g_wpack);
    cudaGetSymbolAddress((void**)&bia, g_bias);
    cudaGetSymbolAddress((void**)&hImg, g_h_img);
    cudaGetSymbolAddress((void**)&hRel, g_h_rel);
    cudaGetSymbolAddress((void**)&hRelB, g_h_relB);
    cudaGetSymbolAddress((void**)&hImgA, g_h_imgA);
    cudaGetSymbolAddress((void**)&hDepA, g_h_depA);
    cudaGetSymbolAddress((void**)&hDepB, g_h_depB);
    cudaGetSymbolAddress((void**)&dsc, g_desc);

    const size_t WB = (size_t)2 * CH * CH * 9;
    const size_t SB = (size_t)CH * HWSZ;

    // 0) pack weights, descriptor table, biases, img fp16
    pack_kernel<<<512, 256>>>(wpk + WP1, dmc_w + 0 * WB, 1152,
                              dmc_w + 2 * WB, 1152, 256);
    pack_kernel<<<512, 256>>>(wpk + WP2, imc_w01, 2304, imc_w23, 1152, 128);
    pack_kernel<<<512, 256>>>(wpk + WP3, rmc_w01, 2304, rmc_w23, 1152, 128);
    pack_kernel<<<512, 256>>>(wpk + WP4, dmc_w + 1 * WB, 1152,
                              dmc_w + 3 * WB, 1152, 256);
    pack_kernel<<<512, 256>>>(wpk + WP5, emb_w1, 2304, (const float*)0, 0, 128);
    pack_kernel<<<512, 256>>>(wpk + WP6, emb_w2, 1152, (const float*)0, 0, 128);
    desc_kernel<<<(3 * SEGCH * 32 + 255) / 256, 256>>>(dsc);

    bias_add<<<1, 256>>>(bia + 0 * 256, dmc_b + 0 * 256, dmc_b + 2 * 256, 256);
    bias_add<<<1, 128>>>(bia + 1 * 256, imc_b01, imc_b23, 128);
    bias_add<<<1, 128>>>(bia + 2 * 256, rmc_b01, rmc_b23, 128);
    bias_add<<<1, 256>>>(bia + 3 * 256, dmc_b + 1 * 256, dmc_b + 3 * 256, 256);
    bias_add<<<1, 128>>>(bia + 4 * 256, emb_b1, (const float*)0, 128);
    bias_add<<<1, 128>>>(bia + 5 * 256, emb_b2, (const float*)0, 128);

    cvt_kernel<<<1024, 256>>>(hImg, img_in, BATCH * CH * HWSZ);

    // 1) rel embedding
    mm_kernel<<<dim3(CH, BATCH), NN>>>(tf,   rw1, rb1, hmid,   CINR, 1);
    mm_kernel<<<dim3(CH, BATCH), NN>>>(hmid, rw2, rb2, relmap, CH,   0);

    // 2) scatter interpolated rows into rel map (fp16 out)
    scatter_kernel<<<dim3(HH, BATCH, 2), 64>>>(relmap, bbox, hRel);

    dim3 g2(HWSZ / CTA_N, 2, BATCH);   // Cout = 256
    dim3 g1(HWSZ / CTA_N, 1, BATCH);   // Cout = 128

    // 3) TriGraph iteration 0
    conv_mma<<<g2, 128>>>(nullptr, hDepB, hImg, hRel, SB, SB,
                          hImg, SB, hRel, SB, nullptr, 0, 2,
                          dsc, wpk + WP1, bia + 0 * 256, 256, 0.5f, 1);
    conv_mma<<<g1, 128>>>(nullptr, hImgA, hImg, nullptr, SB, 0,
                          hImg, SB, hRel, SB, hRel, SB, 3,
                          dsc, wpk + WP2, bia + 1 * 256, 128, 0.5f, 1);
    conv_mma<<<g1, 128>>>(nullptr, hRelB, hRel, nullptr, SB, 0,
                          hImg, SB, hRel, SB, hImg, SB, 3,
                          dsc, wpk + WP3, bia + 2 * 256, 128, 0.5f, 1);

    // 4) TriGraph iteration 1: only dep feeds the output
    conv_mma<<<g2, 128>>>(nullptr, hDepA, hDepB, hDepB + CH * HWSZ,
                          2 * SB, 2 * SB,
                          hImgA, SB, hRelB, SB, nullptr, 0, 2,
                          dsc, wpk + WP4, bia + 3 * 256, 256, 0.5f, 1);

    // 5) final embedding (hImgA dead after step 4 -> reuse); dep split 2 segs
    conv_mma<<<g1, 128>>>(nullptr, hImgA, nullptr, nullptr, 0, 0,
                          hDepA, 2 * SB, hDepA + SB, 2 * SB, nullptr, 0, 2,
                          dsc, wpk + WP5, bia + 4 * 256, 128, 1.f, 1);
    conv_mma<<<g1, 128>>>(out, nullptr, nullptr, nullptr, 0, 0,
                          hImgA, SB, nullptr, 0, nullptr, 0, 1,
                          dsc, wpk + WP6, bia + 5 * 256, 128, 1.f, 0);
}